// round 9
// baseline (speedup 1.0000x reference)
#include <cuda_runtime.h>
#include <cstdint>

// Problem constants (fixed by setup_inputs)
#define NNODES 32768
#define DIM    128
#define NH     4
#define HD     512      // NH*DIM
#define NEDGE  262144
#define NGRAPH 8
#define NPG    4096
#define NCH    8        // chunks per (b,h) for KV partials
#define CHN    512      // nodes per chunk (NPG/NCH)

#define DYN_SMEM 67584  // 128*132*4 (C tile) >= 2*128*40*4 (As+Bs)

// ----------------------------- scratch (static device globals) ---------------
__device__ float g_qs  [NNODES*HD];
__device__ float g_ks  [NNODES*HD];
__device__ float g_cur0[NNODES*HD];
__device__ float g_cur1[NNODES*HD];
__device__ float g_acc [NNODES*HD];
__device__ float g_kvt [32*16384];        // KV^T per (b,h): [e][d]
__device__ float g_pkv [NCH*32*16384];    // KV partials per chunk
__device__ float g_pv  [NCH*4096];        // vsum partials
__device__ float g_vsum[4096];
__device__ float g_ksp [NCH*4096];        // ksum partials
__device__ float g_ksum[4096];
__device__ float g_invden[NNODES*NH];
__device__ float g_dis [NNODES];
__device__ float g_w   [NEDGE];
__device__ int   g_cnt [NNODES];
__device__ int   g_rowptr[NNODES+1];
__device__ int   g_fill[NNODES];
__device__ int   g_bsum[NNODES/256];
__device__ int   g_col [NEDGE];
__device__ int   g_ekey[NEDGE];

// ----------------------------- TF32 helpers ----------------------------------
__device__ __forceinline__ uint32_t tf32r(float x) {
    uint32_t u;
    asm("cvt.rna.tf32.f32 %0, %1;" : "=r"(u) : "f"(x));
    return u;
}

#define MMA_TF32(cc, aa, b0v, b1v)                                              \
    asm volatile("mma.sync.aligned.m16n8k8.row.col.f32.tf32.tf32.f32 "          \
                 "{%0,%1,%2,%3}, {%4,%5,%6,%7}, {%8,%9}, {%0,%1,%2,%3};"        \
                 : "+f"((cc)[0]), "+f"((cc)[1]), "+f"((cc)[2]), "+f"((cc)[3])   \
                 : "r"((aa)[0]), "r"((aa)[1]), "r"((aa)[2]), "r"((aa)[3]),      \
                   "r"(b0v), "r"(b1v))

// MMA mainloop body shared by the three GEMM kernels.
// As[m][k], Bs[n][k] pitch 40; 8 warps (4x2), warp tile 32x64, acc c[2][8][4].
#define GEMM_MAINLOOP(Ab, lda, Bb, ldb, K)                                      \
    for (int kt = 0; kt < (K); kt += 32) {                                      \
        _Pragma("unroll")                                                       \
        for (int r = 0; r < 4; r++) {                                           \
            int idx = tid + r * 256;                                            \
            int row = idx >> 3;                                                 \
            int kq  = (idx & 7) << 2;                                           \
            float4 v = *(const float4*)&(Ab)[(long)(i0 + row) * (lda) + kt + kq]; \
            As[row][kq+0] = tf32r(v.x); As[row][kq+1] = tf32r(v.y);             \
            As[row][kq+2] = tf32r(v.z); As[row][kq+3] = tf32r(v.w);             \
            float4 w = *(const float4*)&(Bb)[(long)(j0 + row) * (ldb) + kt + kq]; \
            Bs[row][kq+0] = tf32r(w.x); Bs[row][kq+1] = tf32r(w.y);             \
            Bs[row][kq+2] = tf32r(w.z); Bs[row][kq+3] = tf32r(w.w);             \
        }                                                                       \
        __syncthreads();                                                        \
        _Pragma("unroll")                                                       \
        for (int ks = 0; ks < 4; ks++) {                                        \
            int k0 = ks * 8;                                                    \
            uint32_t a[2][4];                                                   \
            _Pragma("unroll")                                                   \
            for (int mt = 0; mt < 2; mt++) {                                    \
                int m = mbase + mt * 16 + g;                                    \
                a[mt][0] = As[m    ][k0 + t];                                   \
                a[mt][1] = As[m + 8][k0 + t];                                   \
                a[mt][2] = As[m    ][k0 + t + 4];                               \
                a[mt][3] = As[m + 8][k0 + t + 4];                               \
            }                                                                   \
            _Pragma("unroll")                                                   \
            for (int nt = 0; nt < 8; nt++) {                                    \
                int n = nbase + nt * 8 + g;                                     \
                uint32_t b0 = Bs[n][k0 + t];                                    \
                uint32_t b1 = Bs[n][k0 + t + 4];                                \
                MMA_TF32(c[0][nt], a[0], b0, b1);                               \
                MMA_TF32(c[1][nt], a[1], b0, b1);                               \
            }                                                                   \
        }                                                                       \
        __syncthreads();                                                        \
    }

#define GEMM_PROLOGUE()                                                         \
    int tid = threadIdx.x;                                                      \
    int wid = tid >> 5, lane = tid & 31;                                        \
    int g = lane >> 2, t = lane & 3;                                            \
    int mbase = (wid & 3) * 32, nbase = (wid >> 2) * 64;                        \
    float c[2][8][4];                                                           \
    _Pragma("unroll")                                                           \
    for (int mt = 0; mt < 2; mt++)                                              \
        _Pragma("unroll")                                                       \
        for (int nt = 0; nt < 8; nt++)                                          \
            _Pragma("unroll")                                                   \
            for (int q = 0; q < 4; q++) c[mt][nt][q] = 0.f;

// ----------------------------- generic TC GEMM (output projection) ----------
// C = scale*(A*B^T + bias). Static smem version.
__global__ void gemm_abT_tc(const float* __restrict__ A, int lda,
                            const float* __restrict__ Bm, int ldb,
                            const float* __restrict__ bias,
                            float* __restrict__ C, int ldc,
                            int K, float scale)
{
    __shared__ uint32_t As[128][40];
    __shared__ uint32_t Bs[128][40];
    const float* Ab = A;
    const float* Bb = Bm;
    int i0 = blockIdx.x * 128, j0 = blockIdx.y * 128;
    GEMM_PROLOGUE();
    GEMM_MAINLOOP(Ab, lda, Bb, ldb, K);
#pragma unroll
    for (int mt = 0; mt < 2; mt++) {
        int r0 = i0 + mbase + mt * 16 + g;
#pragma unroll
        for (int nt = 0; nt < 8; nt++) {
            int col = j0 + nbase + nt * 8 + 2 * t;
            float b0 = bias ? bias[col]     : 0.f;
            float b1 = bias ? bias[col + 1] : 0.f;
            float2 o;
            o.x = scale * (c[mt][nt][0] + b0);
            o.y = scale * (c[mt][nt][1] + b1);
            *(float2*)&C[(long)r0 * ldc + col] = o;
            o.x = scale * (c[mt][nt][2] + b0);
            o.y = scale * (c[mt][nt][3] + b1);
            *(float2*)&C[(long)(r0 + 8) * ldc + col] = o;
        }
    }
}

// ----------------------------- projection GEMM + row-normalize epilogue -----
// C = normalize_rows(A*W^T + bias) per head tile. grid (256, 4, 1); blockIdx.y
// is the head (exactly one 128-col tile), so the L2-norm is block-local.
__global__ void gemm_abT_norm(const float* __restrict__ A,
                              const float* __restrict__ Wm,
                              const float* __restrict__ bias,
                              float* __restrict__ C)
{
    extern __shared__ float dyn[];
    uint32_t (*As)[40] = reinterpret_cast<uint32_t(*)[40]>(dyn);
    uint32_t (*Bs)[40] = reinterpret_cast<uint32_t(*)[40]>(dyn + 128 * 40);
    float (*Ct)[132]   = reinterpret_cast<float(*)[132]>(dyn);

    int i0 = blockIdx.x * 128, j0 = blockIdx.y * 128;
    GEMM_PROLOGUE();
    GEMM_MAINLOOP(A, DIM, Wm + (long)j0 * DIM - (long)j0 * DIM, DIM, DIM);
    // (Wm row j0+row handled by j0 offset inside macro via (j0+row)*ldb)

    // stage C tile (+bias) in smem
#pragma unroll
    for (int mt = 0; mt < 2; mt++) {
        int r0 = mbase + mt * 16 + g;
#pragma unroll
        for (int nt = 0; nt < 8; nt++) {
            int col = nbase + nt * 8 + 2 * t;
            float b0 = bias[j0 + col], b1 = bias[j0 + col + 1];
            Ct[r0][col]     = c[mt][nt][0] + b0;
            Ct[r0][col + 1] = c[mt][nt][1] + b1;
            Ct[r0 + 8][col]     = c[mt][nt][2] + b0;
            Ct[r0 + 8][col + 1] = c[mt][nt][3] + b1;
        }
    }
    __syncthreads();

    // per-row L2 normalize; warp handles 16 rows, lane covers 4 cols
    for (int r = 0; r < 16; r++) {
        int row = wid * 16 + r;
        float4 v = *(float4*)&Ct[row][lane * 4];
        float s = v.x*v.x + v.y*v.y + v.z*v.z + v.w*v.w;
#pragma unroll
        for (int o = 16; o; o >>= 1) s += __shfl_xor_sync(0xffffffffu, s, o);
        float rn = rsqrtf(s);
        v.x *= rn; v.y *= rn; v.z *= rn; v.w *= rn;
        *(float4*)&C[(long)(i0 + row) * HD + j0 + lane * 4] = v;
    }
}

// ----------------------------- q·KV GEMM + GCN gather + combine + acc -------
// For one (b,h) and a 128-node tile: tmp = qs_tile @ KV^T (in smem only), then
// curn = 0.5*gather(cur) + 0.5*(tmp+vsum)*invden; acc += curn.
__global__ void gemm_fuse(const float* __restrict__ cur, float* __restrict__ curn)
{
    extern __shared__ float dyn[];
    uint32_t (*As)[40] = reinterpret_cast<uint32_t(*)[40]>(dyn);
    uint32_t (*Bs)[40] = reinterpret_cast<uint32_t(*)[40]>(dyn + 128 * 40);
    float (*Ct)[132]   = reinterpret_cast<float(*)[132]>(dyn);

    int z = blockIdx.z; int zb = z >> 2, zh = z & 3;
    const float* Ab = g_qs + (long)zb * NPG * HD + (long)zh * DIM;  // lda = HD
    const float* Bb = g_kvt + (long)z * 16384;                      // ldb = 128
    int i0 = blockIdx.x * 128, j0 = 0;
    GEMM_PROLOGUE();
    GEMM_MAINLOOP(Ab, HD, Bb, 128, DIM);

    // stage tmp tile in smem
#pragma unroll
    for (int mt = 0; mt < 2; mt++) {
        int r0 = mbase + mt * 16 + g;
#pragma unroll
        for (int nt = 0; nt < 8; nt++) {
            int col = nbase + nt * 8 + 2 * t;
            Ct[r0][col]     = c[mt][nt][0];
            Ct[r0][col + 1] = c[mt][nt][1];
            Ct[r0 + 8][col]     = c[mt][nt][2];
            Ct[r0 + 8][col + 1] = c[mt][nt][3];
        }
    }
    __syncthreads();

    // fused epilogue: warp handles 16 rows (nodes), lane covers 4 e-cols
    int colf = lane * 4;
    float4 vsum4 = *(const float4*)&g_vsum[z * DIM + colf];
    for (int r = 0; r < 16; r++) {
        int row = wid * 16 + r;
        int ig = zb * NPG + i0 + row;              // global node id
        int s = g_rowptr[ig], e = g_rowptr[ig + 1];
        float4 gg = make_float4(0.f, 0.f, 0.f, 0.f);
        for (int p = s; p < e; p++) {
            int cn = g_col[p]; float w = g_w[p];
            float4 a = *(const float4*)&cur[(long)cn * HD + zh * DIM + colf];
            gg.x += w * a.x; gg.y += w * a.y; gg.z += w * a.z; gg.w += w * a.w;
        }
        float id = g_invden[ig * NH + zh];
        float4 tv = *(float4*)&Ct[row][colf];
        float4 rv;
        rv.x = 0.5f * gg.x + 0.5f * ((tv.x + vsum4.x) * id);
        rv.y = 0.5f * gg.y + 0.5f * ((tv.y + vsum4.y) * id);
        rv.z = 0.5f * gg.z + 0.5f * ((tv.z + vsum4.z) * id);
        rv.w = 0.5f * gg.w + 0.5f * ((tv.w + vsum4.w) * id);
        long ob = (long)ig * HD + zh * DIM + colf;
        *(float4*)&curn[ob] = rv;
        float4 av = *(float4*)&g_acc[ob];
        av.x += rv.x; av.y += rv.y; av.z += rv.z; av.w += rv.w;
        *(float4*)&g_acc[ob] = av;
    }
}

// ----------------------------- ksum partials ---------------------------------
__global__ void ksum_partial_kernel()
{
    int chunk = blockIdx.x, bh = blockIdx.y;
    int b = bh >> 2, h = bh & 3, d = threadIdx.x;
    long base = ((long)b * NPG + chunk * CHN) * HD + h * DIM + d;
    float s = 0.f;
    for (int n = 0; n < CHN; n++) s += g_ks[base + (long)n * HD];
    g_ksp[(chunk * 32 + bh) * DIM + d] = s;
}

// deterministic fixed-order reduce of NCH chunk partials
__global__ void reduce_nch(const float* __restrict__ part, float* __restrict__ out, int n)
{
    int i = blockIdx.x * blockDim.x + threadIdx.x;
    if (i < n) {
        float s = 0.f;
#pragma unroll
        for (int c = 0; c < NCH; c++) s += part[(long)c * n + i];
        out[i] = s;
    }
}

// ----------------------------- inverse denominator (loop-invariant) ----------
__global__ void invden_kernel()
{
    int i = blockIdx.x;
    int h = threadIdx.x >> 5, l = threadIdx.x & 31;
    int b = i >> 12;  // /NPG
    float4 q = *(float4*)&g_qs[(long)i * HD + h * DIM + l * 4];
    float4 km = *(float4*)&g_ksum[(b * NH + h) * DIM + l * 4];
    float s = q.x*km.x + q.y*km.y + q.z*km.z + q.w*km.w;
#pragma unroll
    for (int o = 16; o; o >>= 1) s += __shfl_xor_sync(0xffffffffu, s, o);
    if (l == 0) g_invden[i * NH + h] = 1.f / (s + (float)NPG);
}

// ----------------------------- graph prep ------------------------------------
__global__ void count_kernel(const int* __restrict__ ei)
{
    int e = blockIdx.x * blockDim.x + threadIdx.x;
    if (e < NEDGE) atomicAdd(&g_cnt[ei[e]], 1);
}

__global__ void scan1_kernel()
{
    __shared__ int sh[256];
    int tid = threadIdx.x;
    int i = blockIdx.x * 256 + tid;
    int v = g_cnt[i];
    sh[tid] = v;
    __syncthreads();
    for (int o = 1; o < 256; o <<= 1) {
        int t = (tid >= o) ? sh[tid - o] : 0;
        __syncthreads();
        sh[tid] += t;
        __syncthreads();
    }
    g_rowptr[i] = sh[tid] - v;
    if (tid == 255) g_bsum[blockIdx.x] = sh[255];
}

__global__ void scan2_kernel()
{
    __shared__ int sh[128];
    int tid = threadIdx.x;
    int v = g_bsum[tid];
    sh[tid] = v;
    __syncthreads();
    for (int o = 1; o < 128; o <<= 1) {
        int t = (tid >= o) ? sh[tid - o] : 0;
        __syncthreads();
        sh[tid] += t;
        __syncthreads();
    }
    g_bsum[tid] = sh[tid] - v;
}

__global__ void scan3_kernel()
{
    int tid = threadIdx.x;
    int i = blockIdx.x * 256 + tid;
    g_rowptr[i] += g_bsum[blockIdx.x];
    int c = g_cnt[i];
    g_dis[i] = (c > 0) ? rsqrtf((float)c) : 0.f;
    if (i == 0) g_rowptr[NNODES] = NEDGE;
}

__global__ void scatter_kernel(const int* __restrict__ ei)
{
    int e = blockIdx.x * blockDim.x + threadIdx.x;
    if (e < NEDGE) {
        int r = ei[e], c = ei[NEDGE + e];
        int p = g_rowptr[r] + atomicAdd(&g_fill[r], 1);
        g_col[p] = c;
        g_ekey[p] = e;
    }
}

// canonicalize per-row edge order (determinism) + edge weights
__global__ void sortw_kernel()
{
    int i = blockIdx.x * blockDim.x + threadIdx.x;
    if (i >= NNODES) return;
    int s = g_rowptr[i], t = g_rowptr[i + 1];
    int n = t - s;
    float di = g_dis[i];
    if (n > 1 && n <= 64) {
        int kk[64], cc[64];
        for (int j = 0; j < n; j++) { kk[j] = g_ekey[s + j]; cc[j] = g_col[s + j]; }
        for (int a = 1; a < n; a++) {
            int kvv = kk[a], cv = cc[a], b = a - 1;
            while (b >= 0 && kk[b] > kvv) { kk[b+1] = kk[b]; cc[b+1] = cc[b]; b--; }
            kk[b+1] = kvv; cc[b+1] = cv;
        }
        for (int j = 0; j < n; j++) { g_col[s + j] = cc[j]; g_w[s + j] = di * g_dis[cc[j]]; }
    } else {
        for (int j = 0; j < n; j++) g_w[s + j] = di * g_dis[g_col[s + j]];
    }
}

// ----------------------------- init cur = acc = broadcast(x) -----------------
__global__ void init_kernel(const float* __restrict__ x)
{
    long gid = (long)blockIdx.x * blockDim.x + threadIdx.x;
    long f = gid * 4;
    int i = (int)(f >> 9);
    int d = (int)(f & 127);
    float4 v = *(const float4*)&x[(long)i * DIM + d];
    *(float4*)&g_cur0[f] = v;
    *(float4*)&g_acc[f]  = v;
}

// ----------------------------- per-iter: KV^T partials + vsum (tensor core) --
__global__ void kv_partial_tc(const float* __restrict__ cur)
{
    __shared__ uint32_t CU[32][136];   // [node][e]
    __shared__ uint32_t KS[32][136];   // [node][d]
    int chunk = blockIdx.x, bh = blockIdx.y;
    int b = bh >> 2, h = bh & 3;
    long nodeBase = (long)b * NPG + chunk * CHN;
    int tid = threadIdx.x;
    int wid = tid >> 5, lane = tid & 31;
    int g = lane >> 2, t = lane & 3;
    int mbase = (wid & 3) * 32, nbase = (wid >> 2) * 64;

    float c[2][8][4];
#pragma unroll
    for (int mt = 0; mt < 2; mt++)
#pragma unroll
        for (int nt = 0; nt < 8; nt++)
#pragma unroll
            for (int q = 0; q < 4; q++) c[mt][nt][q] = 0.f;
    float4 vs = make_float4(0.f, 0.f, 0.f, 0.f);

    for (int t0 = 0; t0 < CHN; t0 += 32) {
#pragma unroll
        for (int r = 0; r < 4; r++) {
            int idx = tid + r * 256;
            int nn = idx >> 5;
            int c4 = (idx & 31) * 4;
            long off = (nodeBase + t0 + nn) * HD + h * DIM + c4;
            float4 u  = *(const float4*)&cur[off];
            float4 k4 = *(const float4*)&g_ks[off];
            vs.x += u.x; vs.y += u.y; vs.z += u.z; vs.w += u.w;
            CU[nn][c4+0] = tf32r(u.x);  CU[nn][c4+1] = tf32r(u.y);
            CU[nn][c4+2] = tf32r(u.z);  CU[nn][c4+3] = tf32r(u.w);
            KS[nn][c4+0] = tf32r(k4.x); KS[nn][c4+1] = tf32r(k4.y);
            KS[nn][c4+2] = tf32r(k4.z); KS[nn][c4+3] = tf32r(k4.w);
        }
        __syncthreads();
#pragma unroll
        for (int ks = 0; ks < 4; ks++) {
            int k0 = ks * 8;
            uint32_t a[2][4];
#pragma unroll
            for (int mt = 0; mt < 2; mt++) {
                int m = mbase + mt * 16 + g;
                a[mt][0] = CU[k0 + t    ][m];
                a[mt][1] = CU[k0 + t    ][m + 8];
                a[mt][2] = CU[k0 + t + 4][m];
                a[mt][3] = CU[k0 + t + 4][m + 8];
            }
#pragma unroll
            for (int nt = 0; nt < 8; nt++) {
                int n = nbase + nt * 8 + g;
                uint32_t b0 = KS[k0 + t    ][n];
                uint32_t b1 = KS[k0 + t + 4][n];
                MMA_TF32(c[0][nt], a[0], b0, b1);
                MMA_TF32(c[1][nt], a[1], b0, b1);
            }
        }
        __syncthreads();
    }

    // vsum partial: fixed-order 8-way smem reduce
    {
        int cb = (tid & 31) * 4, rv = tid >> 5;
        CU[rv][cb+0] = __float_as_uint(vs.x);
        CU[rv][cb+1] = __float_as_uint(vs.y);
        CU[rv][cb+2] = __float_as_uint(vs.z);
        CU[rv][cb+3] = __float_as_uint(vs.w);
    }
    __syncthreads();
    if (tid < 128) {
        float s = 0.f;
#pragma unroll
        for (int j = 0; j < 8; j++) s += __uint_as_float(CU[j][tid]);
        g_pv[(chunk * 32 + bh) * 128 + tid] = s;
    }

    long base = ((long)chunk * 32 + bh) * 16384;
#pragma unroll
    for (int mt = 0; mt < 2; mt++) {
        int r0 = mbase + mt * 16 + g;
#pragma unroll
        for (int nt = 0; nt < 8; nt++) {
            int col = nbase + nt * 8 + 2 * t;
            float2 o;
            o.x = c[mt][nt][0]; o.y = c[mt][nt][1];
            *(float2*)&g_pkv[base + (long)r0 * 128 + col] = o;
            o.x = c[mt][nt][2]; o.y = c[mt][nt][3];
            *(float2*)&g_pkv[base + (long)(r0 + 8) * 128 + col] = o;
        }
    }
}

// ----------------------------- host orchestration ----------------------------
extern "C" void kernel_launch(void* const* d_in, const int* in_sizes, int n_in,
                              void* d_out, int out_size)
{
    const float* x    = (const float*)d_in[0];
    const float* Wq_w = (const float*)d_in[1];
    const float* Wq_b = (const float*)d_in[2];
    const float* Wk_w = (const float*)d_in[3];
    const float* Wk_b = (const float*)d_in[4];
    const float* Wo_w = (const float*)d_in[5];
    const float* Wo_b = (const float*)d_in[6];
    const int*   ei   = (const int*)  d_in[7];
    float* out = (float*)d_out;

    float *qs, *ks, *cur0, *cur1, *acc, *kvt, *pkv, *pv, *vsum, *ksp, *ksum;
    int *cnt, *fill;
    cudaGetSymbolAddress((void**)&qs,   g_qs);
    cudaGetSymbolAddress((void**)&ks,   g_ks);
    cudaGetSymbolAddress((void**)&cur0, g_cur0);
    cudaGetSymbolAddress((void**)&cur1, g_cur1);
    cudaGetSymbolAddress((void**)&acc,  g_acc);
    cudaGetSymbolAddress((void**)&kvt,  g_kvt);
    cudaGetSymbolAddress((void**)&pkv,  g_pkv);
    cudaGetSymbolAddress((void**)&pv,   g_pv);
    cudaGetSymbolAddress((void**)&vsum, g_vsum);
    cudaGetSymbolAddress((void**)&ksp,  g_ksp);
    cudaGetSymbolAddress((void**)&ksum, g_ksum);
    cudaGetSymbolAddress((void**)&cnt,  g_cnt);
    cudaGetSymbolAddress((void**)&fill, g_fill);

    cudaFuncSetAttribute(gemm_abT_norm, cudaFuncAttributeMaxDynamicSharedMemorySize, DYN_SMEM);
    cudaFuncSetAttribute(gemm_fuse,     cudaFuncAttributeMaxDynamicSharedMemorySize, DYN_SMEM);

    // Q/K projections fused with per-head row normalization
    gemm_abT_norm<<<dim3(256,4,1),256,DYN_SMEM>>>(x, Wq_w, Wq_b, qs);
    gemm_abT_norm<<<dim3(256,4,1),256,DYN_SMEM>>>(x, Wk_w, Wk_b, ks);
    ksum_partial_kernel<<<dim3(NCH,32),128>>>();
    reduce_nch<<<16,256>>>(ksp, ksum, 4096);
    invden_kernel<<<NNODES,128>>>();

    // Graph prep: degrees, CSR, normalized weights (deterministic order)
    cudaMemsetAsync(cnt,  0, NNODES * sizeof(int));
    cudaMemsetAsync(fill, 0, NNODES * sizeof(int));
    count_kernel<<<NEDGE/256,256>>>(ei);
    scan1_kernel<<<NNODES/256,256>>>();
    scan2_kernel<<<1,128>>>();
    scan3_kernel<<<NNODES/256,256>>>();
    scatter_kernel<<<NEDGE/256,256>>>(ei);
    sortw_kernel<<<NNODES/128,128>>>();

    // cur = acc = broadcast(x) over heads
    init_kernel<<<16384,256>>>(x);

    float* curA = cur0; float* curB = cur1;
    for (int it = 0; it < 4; it++) {
        kv_partial_tc<<<dim3(NCH,32),256>>>(curA);
        reduce_nch<<<2048,256>>>(pkv, kvt, 32*16384);
        reduce_nch<<<16,256>>>(pv, vsum, 4096);
        gemm_fuse<<<dim3(32,1,32),256,DYN_SMEM>>>(curA, curB);
        float* sw = curA; curA = curB; curB = sw;
    }

    // out = (acc @ Wo^T + Wo_b) / H
    gemm_abT_tc<<<dim3(256,1,1),256>>>(acc, HD, Wo_w, HD, Wo_b, out, DIM, HD, 0.25f);
    (void)in_sizes; (void)n_in; (void)out_size;
}

// round 11
// speedup vs baseline: 1.2840x; 1.2840x over previous
#include <cuda_runtime.h>
#include <cstdint>

// Problem constants (fixed by setup_inputs)
#define NNODES 32768
#define DIM    128
#define NH     4
#define HD     512      // NH*DIM
#define NEDGE  262144
#define NGRAPH 8
#define NPG    4096
#define NCH    8        // chunks per (b,h) for KV partials
#define CHN    512      // nodes per chunk (NPG/NCH)

// ----------------------------- scratch (static device globals) ---------------
__device__ float g_qs  [NNODES*HD];
__device__ float g_ks  [NNODES*HD];
__device__ float g_cur0[NNODES*HD];
__device__ float g_cur1[NNODES*HD];
__device__ float g_acc [NNODES*HD];
__device__ float g_tmp [NNODES*HD];
__device__ float g_kvt [32*16384];        // KV^T per (b,h): [e][d]
__device__ float g_pkv [NCH*32*16384];    // KV partials per chunk
__device__ float g_pv  [NCH*4096];        // vsum partials
__device__ float g_vsum[4096];
__device__ float g_ksp [NCH*4096];        // ksum partials
__device__ float g_ksum[4096];
__device__ float g_invden[NNODES*NH];
__device__ float g_dis [NNODES];
__device__ float g_w   [NEDGE];
__device__ int   g_cnt [NNODES];
__device__ int   g_rowptr[NNODES+1];
__device__ int   g_fill[NNODES];
__device__ int   g_bsum[NNODES/256];
__device__ int   g_col [NEDGE];
__device__ int   g_ekey[NEDGE];

// ----------------------------- TF32 helpers ----------------------------------
__device__ __forceinline__ uint32_t tf32r(float x) {
    uint32_t u;
    asm("cvt.rna.tf32.f32 %0, %1;" : "=r"(u) : "f"(x));
    return u;
}

#define MMA_TF32(cc, aa, b0v, b1v)                                              \
    asm volatile("mma.sync.aligned.m16n8k8.row.col.f32.tf32.tf32.f32 "          \
                 "{%0,%1,%2,%3}, {%4,%5,%6,%7}, {%8,%9}, {%0,%1,%2,%3};"        \
                 : "+f"((cc)[0]), "+f"((cc)[1]), "+f"((cc)[2]), "+f"((cc)[3])   \
                 : "r"((aa)[0]), "r"((aa)[1]), "r"((aa)[2]), "r"((aa)[3]),      \
                   "r"(b0v), "r"(b1v))

// MMA mainloop body shared by the GEMM kernels.
// As[m][k], Bs[n][k] pitch 40; 8 warps (4x2), warp tile 32x64, acc c[2][8][4].
#define GEMM_MAINLOOP(Ab, lda, Bb, ldb, K)                                      \
    for (int kt = 0; kt < (K); kt += 32) {                                      \
        _Pragma("unroll")                                                       \
        for (int r = 0; r < 4; r++) {                                           \
            int idx = tid + r * 256;                                            \
            int row = idx >> 3;                                                 \
            int kq  = (idx & 7) << 2;                                           \
            float4 v = *(const float4*)&(Ab)[(long)(i0 + row) * (lda) + kt + kq]; \
            As[row][kq+0] = tf32r(v.x); As[row][kq+1] = tf32r(v.y);             \
            As[row][kq+2] = tf32r(v.z); As[row][kq+3] = tf32r(v.w);             \
            float4 w = *(const float4*)&(Bb)[(long)(j0 + row) * (ldb) + kt + kq]; \
            Bs[row][kq+0] = tf32r(w.x); Bs[row][kq+1] = tf32r(w.y);             \
            Bs[row][kq+2] = tf32r(w.z); Bs[row][kq+3] = tf32r(w.w);             \
        }                                                                       \
        __syncthreads();                                                        \
        _Pragma("unroll")                                                       \
        for (int ks = 0; ks < 4; ks++) {                                        \
            int k0 = ks * 8;                                                    \
            uint32_t a[2][4];                                                   \
            _Pragma("unroll")                                                   \
            for (int mt = 0; mt < 2; mt++) {                                    \
                int m = mbase + mt * 16 + g;                                    \
                a[mt][0] = As[m    ][k0 + t];                                   \
                a[mt][1] = As[m + 8][k0 + t];                                   \
                a[mt][2] = As[m    ][k0 + t + 4];                               \
                a[mt][3] = As[m + 8][k0 + t + 4];                               \
            }                                                                   \
            _Pragma("unroll")                                                   \
            for (int nt = 0; nt < 8; nt++) {                                    \
                int n = nbase + nt * 8 + g;                                     \
                uint32_t b0 = Bs[n][k0 + t];                                    \
                uint32_t b1 = Bs[n][k0 + t + 4];                                \
                MMA_TF32(c[0][nt], a[0], b0, b1);                               \
                MMA_TF32(c[1][nt], a[1], b0, b1);                               \
            }                                                                   \
        }                                                                       \
        __syncthreads();                                                        \
    }

#define GEMM_PROLOGUE()                                                         \
    int tid = threadIdx.x;                                                      \
    int wid = tid >> 5, lane = tid & 31;                                        \
    int g = lane >> 2, t = lane & 3;                                            \
    int mbase = (wid & 3) * 32, nbase = (wid >> 2) * 64;                        \
    float c[2][8][4];                                                           \
    _Pragma("unroll")                                                           \
    for (int mt = 0; mt < 2; mt++)                                              \
        _Pragma("unroll")                                                       \
        for (int nt = 0; nt < 8; nt++)                                          \
            _Pragma("unroll")                                                   \
            for (int q = 0; q < 4; q++) c[mt][nt][q] = 0.f;

// ----------------------------- generic TC GEMM: C = scale*(A*B^T + bias) -----
// Batched over blockIdx.z with (b,h) split strides. Static 40KB smem.
__global__ void gemm_abT_tc(const float* __restrict__ A, int lda, long sOutA, long sInA,
                            const float* __restrict__ Bm, int ldb, long sOutB, long sInB,
                            const float* __restrict__ bias,
                            float* __restrict__ C, int ldc, long sOutC, long sInC,
                            int K, float scale)
{
    __shared__ uint32_t As[128][40];
    __shared__ uint32_t Bs[128][40];
    int z = blockIdx.z; int zb = z >> 2, zh = z & 3;
    const float* Ab = A  + zb*sOutA + zh*sInA;
    const float* Bb = Bm + zb*sOutB + zh*sInB;
    float*       Cb = C  + zb*sOutC + zh*sInC;
    int i0 = blockIdx.x * 128, j0 = blockIdx.y * 128;
    GEMM_PROLOGUE();
    GEMM_MAINLOOP(Ab, lda, Bb, ldb, K);
#pragma unroll
    for (int mt = 0; mt < 2; mt++) {
        int r0 = i0 + mbase + mt * 16 + g;
#pragma unroll
        for (int nt = 0; nt < 8; nt++) {
            int col = j0 + nbase + nt * 8 + 2 * t;
            float b0 = bias ? bias[col]     : 0.f;
            float b1 = bias ? bias[col + 1] : 0.f;
            float2 o;
            o.x = scale * (c[mt][nt][0] + b0);
            o.y = scale * (c[mt][nt][1] + b1);
            *(float2*)&Cb[(long)r0 * ldc + col] = o;
            o.x = scale * (c[mt][nt][2] + b0);
            o.y = scale * (c[mt][nt][3] + b1);
            *(float2*)&Cb[(long)(r0 + 8) * ldc + col] = o;
        }
    }
}

// ----------------------------- projection GEMM + register-space row norm -----
// C = normalize_rows(A*W^T + bias) per head. grid (256, NH); blockIdx.y = head
// (one 128-col tile == one head), so the row L2-norm is block-local.
// Norm computed from MMA fragments: fragment-local ssq -> shuffle over t ->
// 1KB smem cross-warp-half exchange. Occupancy identical to plain GEMM.
__global__ void gemm_abT_norm(const float* __restrict__ A,
                              const float* __restrict__ Wm,
                              const float* __restrict__ bias,
                              float* __restrict__ C)
{
    __shared__ uint32_t As[128][40];
    __shared__ uint32_t Bs[128][40];
    __shared__ float nrm[2][128];
    int i0 = blockIdx.x * 128, j0 = blockIdx.y * 128;
    GEMM_PROLOGUE();
    GEMM_MAINLOOP(A, DIM, Wm, DIM, DIM);

    int ng = wid >> 2;
    // add bias into fragments, accumulate per-row sum of squares
    float ss[2][2] = {{0.f,0.f},{0.f,0.f}};
#pragma unroll
    for (int mt = 0; mt < 2; mt++)
#pragma unroll
        for (int nt = 0; nt < 8; nt++) {
            int col = j0 + nbase + nt * 8 + 2 * t;
            float b0 = bias[col], b1 = bias[col + 1];
            c[mt][nt][0] += b0; c[mt][nt][1] += b1;
            c[mt][nt][2] += b0; c[mt][nt][3] += b1;
            ss[mt][0] += c[mt][nt][0]*c[mt][nt][0] + c[mt][nt][1]*c[mt][nt][1];
            ss[mt][1] += c[mt][nt][2]*c[mt][nt][2] + c[mt][nt][3]*c[mt][nt][3];
        }
    // reduce over the 4 t-lanes (same g) -> per-row partial over this warp's 64 cols
#pragma unroll
    for (int mt = 0; mt < 2; mt++)
#pragma unroll
        for (int hq = 0; hq < 2; hq++) {
            float v = ss[mt][hq];
            v += __shfl_xor_sync(0xffffffffu, v, 1);
            v += __shfl_xor_sync(0xffffffffu, v, 2);
            ss[mt][hq] = v;
        }
    if (t == 0) {
        nrm[ng][mbase + g]      = ss[0][0];
        nrm[ng][mbase + g + 8]  = ss[0][1];
        nrm[ng][mbase + 16 + g] = ss[1][0];
        nrm[ng][mbase + 24 + g] = ss[1][1];
    }
    __syncthreads();
    float rn[2][2];
    rn[0][0] = rsqrtf(nrm[0][mbase + g]      + nrm[1][mbase + g]);
    rn[0][1] = rsqrtf(nrm[0][mbase + g + 8]  + nrm[1][mbase + g + 8]);
    rn[1][0] = rsqrtf(nrm[0][mbase + 16 + g] + nrm[1][mbase + 16 + g]);
    rn[1][1] = rsqrtf(nrm[0][mbase + 24 + g] + nrm[1][mbase + 24 + g]);

#pragma unroll
    for (int mt = 0; mt < 2; mt++) {
        int r0 = i0 + mbase + mt * 16 + g;
#pragma unroll
        for (int nt = 0; nt < 8; nt++) {
            int col = j0 + nbase + nt * 8 + 2 * t;
            float2 o;
            o.x = c[mt][nt][0] * rn[mt][0];
            o.y = c[mt][nt][1] * rn[mt][0];
            *(float2*)&C[(long)r0 * HD + col] = o;
            o.x = c[mt][nt][2] * rn[mt][1];
            o.y = c[mt][nt][3] * rn[mt][1];
            *(float2*)&C[(long)(r0 + 8) * HD + col] = o;
        }
    }
}

// ----------------------------- ksum partials ---------------------------------
__global__ void ksum_partial_kernel()
{
    int chunk = blockIdx.x, bh = blockIdx.y;
    int b = bh >> 2, h = bh & 3, d = threadIdx.x;
    long base = ((long)b * NPG + chunk * CHN) * HD + h * DIM + d;
    float s = 0.f;
    for (int n = 0; n < CHN; n++) s += g_ks[base + (long)n * HD];
    g_ksp[(chunk * 32 + bh) * DIM + d] = s;
}

// deterministic fixed-order reduce of NCH chunk partials
__global__ void reduce_nch(const float* __restrict__ part, float* __restrict__ out, int n)
{
    int i = blockIdx.x * blockDim.x + threadIdx.x;
    if (i < n) {
        float s = 0.f;
#pragma unroll
        for (int c = 0; c < NCH; c++) s += part[(long)c * n + i];
        out[i] = s;
    }
}

// ----------------------------- inverse denominator (loop-invariant) ----------
__global__ void invden_kernel()
{
    int i = blockIdx.x;
    int h = threadIdx.x >> 5, l = threadIdx.x & 31;
    int b = i >> 12;  // /NPG
    float4 q = *(float4*)&g_qs[(long)i * HD + h * DIM + l * 4];
    float4 km = *(float4*)&g_ksum[(b * NH + h) * DIM + l * 4];
    float s = q.x*km.x + q.y*km.y + q.z*km.z + q.w*km.w;
#pragma unroll
    for (int o = 16; o; o >>= 1) s += __shfl_xor_sync(0xffffffffu, s, o);
    if (l == 0) g_invden[i * NH + h] = 1.f / (s + (float)NPG);
}

// ----------------------------- graph prep ------------------------------------
__global__ void count_kernel(const int* __restrict__ ei)
{
    int e = blockIdx.x * blockDim.x + threadIdx.x;
    if (e < NEDGE) atomicAdd(&g_cnt[ei[e]], 1);
}

__global__ void scan1_kernel()
{
    __shared__ int sh[256];
    int tid = threadIdx.x;
    int i = blockIdx.x * 256 + tid;
    int v = g_cnt[i];
    sh[tid] = v;
    __syncthreads();
    for (int o = 1; o < 256; o <<= 1) {
        int t = (tid >= o) ? sh[tid - o] : 0;
        __syncthreads();
        sh[tid] += t;
        __syncthreads();
    }
    g_rowptr[i] = sh[tid] - v;
    if (tid == 255) g_bsum[blockIdx.x] = sh[255];
}

__global__ void scan2_kernel()
{
    __shared__ int sh[128];
    int tid = threadIdx.x;
    int v = g_bsum[tid];
    sh[tid] = v;
    __syncthreads();
    for (int o = 1; o < 128; o <<= 1) {
        int t = (tid >= o) ? sh[tid - o] : 0;
        __syncthreads();
        sh[tid] += t;
        __syncthreads();
    }
    g_bsum[tid] = sh[tid] - v;
}

__global__ void scan3_kernel()
{
    int tid = threadIdx.x;
    int i = blockIdx.x * 256 + tid;
    g_rowptr[i] += g_bsum[blockIdx.x];
    int c = g_cnt[i];
    g_dis[i] = (c > 0) ? rsqrtf((float)c) : 0.f;
    if (i == 0) g_rowptr[NNODES] = NEDGE;
}

__global__ void scatter_kernel(const int* __restrict__ ei)
{
    int e = blockIdx.x * blockDim.x + threadIdx.x;
    if (e < NEDGE) {
        int r = ei[e], c = ei[NEDGE + e];
        int p = g_rowptr[r] + atomicAdd(&g_fill[r], 1);
        g_col[p] = c;
        g_ekey[p] = e;
    }
}

// canonicalize per-row edge order (determinism) + edge weights
__global__ void sortw_kernel()
{
    int i = blockIdx.x * blockDim.x + threadIdx.x;
    if (i >= NNODES) return;
    int s = g_rowptr[i], t = g_rowptr[i + 1];
    int n = t - s;
    float di = g_dis[i];
    if (n > 1 && n <= 64) {
        int kk[64], cc[64];
        for (int j = 0; j < n; j++) { kk[j] = g_ekey[s + j]; cc[j] = g_col[s + j]; }
        for (int a = 1; a < n; a++) {
            int kvv = kk[a], cv = cc[a], b = a - 1;
            while (b >= 0 && kk[b] > kvv) { kk[b+1] = kk[b]; cc[b+1] = cc[b]; b--; }
            kk[b+1] = kvv; cc[b+1] = cv;
        }
        for (int j = 0; j < n; j++) { g_col[s + j] = cc[j]; g_w[s + j] = di * g_dis[cc[j]]; }
    } else {
        for (int j = 0; j < n; j++) g_w[s + j] = di * g_dis[g_col[s + j]];
    }
}

// ----------------------------- init cur = acc = broadcast(x) -----------------
__global__ void init_kernel(const float* __restrict__ x)
{
    long gid = (long)blockIdx.x * blockDim.x + threadIdx.x;
    long f = gid * 4;
    int i = (int)(f >> 9);
    int d = (int)(f & 127);
    float4 v = *(const float4*)&x[(long)i * DIM + d];
    *(float4*)&g_cur0[f] = v;
    *(float4*)&g_acc[f]  = v;
}

// ----------------------------- per-iter: KV^T partials + vsum (tensor core) --
__global__ void kv_partial_tc(const float* __restrict__ cur)
{
    __shared__ uint32_t CU[32][136];   // [node][e]
    __shared__ uint32_t KS[32][136];   // [node][d]
    int chunk = blockIdx.x, bh = blockIdx.y;
    int b = bh >> 2, h = bh & 3;
    long nodeBase = (long)b * NPG + chunk * CHN;
    int tid = threadIdx.x;
    int wid = tid >> 5, lane = tid & 31;
    int g = lane >> 2, t = lane & 3;
    int mbase = (wid & 3) * 32, nbase = (wid >> 2) * 64;

    float c[2][8][4];
#pragma unroll
    for (int mt = 0; mt < 2; mt++)
#pragma unroll
        for (int nt = 0; nt < 8; nt++)
#pragma unroll
            for (int q = 0; q < 4; q++) c[mt][nt][q] = 0.f;
    float4 vs = make_float4(0.f, 0.f, 0.f, 0.f);

    for (int t0 = 0; t0 < CHN; t0 += 32) {
#pragma unroll
        for (int r = 0; r < 4; r++) {
            int idx = tid + r * 256;
            int nn = idx >> 5;
            int c4 = (idx & 31) * 4;
            long off = (nodeBase + t0 + nn) * HD + h * DIM + c4;
            float4 u  = *(const float4*)&cur[off];
            float4 k4 = *(const float4*)&g_ks[off];
            vs.x += u.x; vs.y += u.y; vs.z += u.z; vs.w += u.w;
            CU[nn][c4+0] = tf32r(u.x);  CU[nn][c4+1] = tf32r(u.y);
            CU[nn][c4+2] = tf32r(u.z);  CU[nn][c4+3] = tf32r(u.w);
            KS[nn][c4+0] = tf32r(k4.x); KS[nn][c4+1] = tf32r(k4.y);
            KS[nn][c4+2] = tf32r(k4.z); KS[nn][c4+3] = tf32r(k4.w);
        }
        __syncthreads();
#pragma unroll
        for (int ks = 0; ks < 4; ks++) {
            int k0 = ks * 8;
            uint32_t a[2][4];
#pragma unroll
            for (int mt = 0; mt < 2; mt++) {
                int m = mbase + mt * 16 + g;
                a[mt][0] = CU[k0 + t    ][m];
                a[mt][1] = CU[k0 + t    ][m + 8];
                a[mt][2] = CU[k0 + t + 4][m];
                a[mt][3] = CU[k0 + t + 4][m + 8];
            }
#pragma unroll
            for (int nt = 0; nt < 8; nt++) {
                int n = nbase + nt * 8 + g;
                uint32_t b0 = KS[k0 + t    ][n];
                uint32_t b1 = KS[k0 + t + 4][n];
                MMA_TF32(c[0][nt], a[0], b0, b1);
                MMA_TF32(c[1][nt], a[1], b0, b1);
            }
        }
        __syncthreads();
    }

    // vsum partial: fixed-order 8-way smem reduce
    {
        int cb = (tid & 31) * 4, rv = tid >> 5;
        CU[rv][cb+0] = __float_as_uint(vs.x);
        CU[rv][cb+1] = __float_as_uint(vs.y);
        CU[rv][cb+2] = __float_as_uint(vs.z);
        CU[rv][cb+3] = __float_as_uint(vs.w);
    }
    __syncthreads();
    if (tid < 128) {
        float s = 0.f;
#pragma unroll
        for (int j = 0; j < 8; j++) s += __uint_as_float(CU[j][tid]);
        g_pv[(chunk * 32 + bh) * 128 + tid] = s;
    }

    long base = ((long)chunk * 32 + bh) * 16384;
#pragma unroll
    for (int mt = 0; mt < 2; mt++) {
        int r0 = mbase + mt * 16 + g;
#pragma unroll
        for (int nt = 0; nt < 8; nt++) {
            int col = nbase + nt * 8 + 2 * t;
            float2 o;
            o.x = c[mt][nt][0]; o.y = c[mt][nt][1];
            *(float2*)&g_pkv[base + (long)r0 * 128 + col] = o;
            o.x = c[mt][nt][2]; o.y = c[mt][nt][3];
            *(float2*)&g_pkv[base + (long)(r0 + 8) * 128 + col] = o;
        }
    }
}

// ----------------------------- per-iter: GCN gather + attn combine + acc -----
__global__ void fuse_kernel(const float* __restrict__ cur, float* __restrict__ curn)
{
    int slot = threadIdx.x >> 6;       // 4 nodes per block
    int t = threadIdx.x & 63;          // 64 threads per node
    int i = blockIdx.x * 4 + slot;
    int b = i >> 12;
    int f0 = t * 4, f1 = t * 4 + 256;
    int s = g_rowptr[i], e = g_rowptr[i + 1];

    float4 gg0 = make_float4(0,0,0,0), gg1 = make_float4(0,0,0,0);
    for (int p = s; p < e; p++) {
        int c = g_col[p]; float w = g_w[p];
        const float* cr = cur + (long)c * HD;
        float4 a0 = *(const float4*)&cr[f0];
        float4 a1 = *(const float4*)&cr[f1];
        gg0.x += w * a0.x; gg0.y += w * a0.y; gg0.z += w * a0.z; gg0.w += w * a0.w;
        gg1.x += w * a1.x; gg1.y += w * a1.y; gg1.z += w * a1.z; gg1.w += w * a1.w;
    }
    int h0 = f0 >> 7, h1 = f1 >> 7;
    float id0 = g_invden[i * NH + h0];
    float id1 = g_invden[i * NH + h1];
    long ib = (long)i * HD;
    float4 t0 = *(const float4*)&g_tmp[ib + f0];
    float4 t1 = *(const float4*)&g_tmp[ib + f1];
    float4 v0 = *(const float4*)&g_vsum[(b * NH + h0) * DIM + (f0 & 127)];
    float4 v1 = *(const float4*)&g_vsum[(b * NH + h1) * DIM + (f1 & 127)];

    float4 r0, r1;
    r0.x = 0.5f*gg0.x + 0.5f*((t0.x + v0.x) * id0);
    r0.y = 0.5f*gg0.y + 0.5f*((t0.y + v0.y) * id0);
    r0.z = 0.5f*gg0.z + 0.5f*((t0.z + v0.z) * id0);
    r0.w = 0.5f*gg0.w + 0.5f*((t0.w + v0.w) * id0);
    r1.x = 0.5f*gg1.x + 0.5f*((t1.x + v1.x) * id1);
    r1.y = 0.5f*gg1.y + 0.5f*((t1.y + v1.y) * id1);
    r1.z = 0.5f*gg1.z + 0.5f*((t1.z + v1.z) * id1);
    r1.w = 0.5f*gg1.w + 0.5f*((t1.w + v1.w) * id1);

    *(float4*)&curn[ib + f0] = r0;
    *(float4*)&curn[ib + f1] = r1;

    float4 a0 = *(float4*)&g_acc[ib + f0];
    a0.x += r0.x; a0.y += r0.y; a0.z += r0.z; a0.w += r0.w;
    *(float4*)&g_acc[ib + f0] = a0;
    float4 a1 = *(float4*)&g_acc[ib + f1];
    a1.x += r1.x; a1.y += r1.y; a1.z += r1.z; a1.w += r1.w;
    *(float4*)&g_acc[ib + f1] = a1;
}

// ----------------------------- host orchestration ----------------------------
extern "C" void kernel_launch(void* const* d_in, const int* in_sizes, int n_in,
                              void* d_out, int out_size)
{
    const float* x    = (const float*)d_in[0];
    const float* Wq_w = (const float*)d_in[1];
    const float* Wq_b = (const float*)d_in[2];
    const float* Wk_w = (const float*)d_in[3];
    const float* Wk_b = (const float*)d_in[4];
    const float* Wo_w = (const float*)d_in[5];
    const float* Wo_b = (const float*)d_in[6];
    const int*   ei   = (const int*)  d_in[7];
    float* out = (float*)d_out;

    float *qs, *ks, *cur0, *cur1, *acc, *tmp, *kvt, *pkv, *pv, *vsum, *ksp, *ksum;
    int *cnt, *fill;
    cudaGetSymbolAddress((void**)&qs,   g_qs);
    cudaGetSymbolAddress((void**)&ks,   g_ks);
    cudaGetSymbolAddress((void**)&cur0, g_cur0);
    cudaGetSymbolAddress((void**)&cur1, g_cur1);
    cudaGetSymbolAddress((void**)&acc,  g_acc);
    cudaGetSymbolAddress((void**)&tmp,  g_tmp);
    cudaGetSymbolAddress((void**)&kvt,  g_kvt);
    cudaGetSymbolAddress((void**)&pkv,  g_pkv);
    cudaGetSymbolAddress((void**)&pv,   g_pv);
    cudaGetSymbolAddress((void**)&vsum, g_vsum);
    cudaGetSymbolAddress((void**)&ksp,  g_ksp);
    cudaGetSymbolAddress((void**)&ksum, g_ksum);
    cudaGetSymbolAddress((void**)&cnt,  g_cnt);
    cudaGetSymbolAddress((void**)&fill, g_fill);

    // Q/K projections fused with per-head row normalization (register-space)
    gemm_abT_norm<<<dim3(256,4,1),256>>>(x, Wq_w, Wq_b, qs);
    gemm_abT_norm<<<dim3(256,4,1),256>>>(x, Wk_w, Wk_b, ks);
    ksum_partial_kernel<<<dim3(NCH,32),128>>>();
    reduce_nch<<<16,256>>>(ksp, ksum, 4096);
    invden_kernel<<<NNODES,128>>>();

    // Graph prep: degrees, CSR, normalized weights (deterministic order)
    cudaMemsetAsync(cnt,  0, NNODES * sizeof(int));
    cudaMemsetAsync(fill, 0, NNODES * sizeof(int));
    count_kernel<<<NEDGE/256,256>>>(ei);
    scan1_kernel<<<NNODES/256,256>>>();
    scan2_kernel<<<1,128>>>();
    scan3_kernel<<<NNODES/256,256>>>();
    scatter_kernel<<<NEDGE/256,256>>>(ei);
    sortw_kernel<<<NNODES/128,128>>>();

    // cur = acc = broadcast(x) over heads
    init_kernel<<<16384,256>>>(x);

    float* curA = cur0; float* curB = cur1;
    for (int it = 0; it < 4; it++) {
        kv_partial_tc<<<dim3(NCH,32),256>>>(curA);
        reduce_nch<<<2048,256>>>(pkv, kvt, 32*16384);
        reduce_nch<<<16,256>>>(pv, vsum, 4096);
        // tmp[n, h*128+e] = qs[n, h*128+:] @ KV  (batched over 32 (b,h))
        gemm_abT_tc<<<dim3(32,1,32),256>>>(qs, HD, (long)NPG*HD, DIM,
                                           kvt, DIM, 4L*16384, 16384,
                                           nullptr,
                                           tmp, HD, (long)NPG*HD, DIM,
                                           DIM, 1.f);
        fuse_kernel<<<NNODES/4,256>>>(curA, curB);
        float* sw = curA; curA = curB; curB = sw;
    }

    // out = (acc @ Wo^T + Wo_b) / H
    gemm_abT_tc<<<dim3(256,1,1),256>>>(acc, HD, 0, 0, Wo_w, HD, 0, 0, Wo_b,
                                       out, DIM, 0, 0, HD, 0.25f);
    (void)in_sizes; (void)n_in; (void)out_size;
}

// round 12
// speedup vs baseline: 1.3254x; 1.0323x over previous
#include <cuda_runtime.h>
#include <cstdint>

// Problem constants (fixed by setup_inputs)
#define NNODES 32768
#define DIM    128
#define NH     4
#define HD     512      // NH*DIM
#define NEDGE  262144
#define NGRAPH 8
#define NPG    4096
#define NCH    8        // chunks per (b,h) for KV partials
#define CHN    512      // nodes per chunk (NPG/NCH)

// ----------------------------- scratch (static device globals) ---------------
__device__ float g_qs  [NNODES*HD];
__device__ float g_ks  [NNODES*HD];
__device__ float g_cur0[NNODES*HD];     // iterate: cur_t, t=0..4 (0 = x broadcast)
__device__ float g_cur1[NNODES*HD];
__device__ float g_cur2[NNODES*HD];
__device__ float g_cur3[NNODES*HD];
__device__ float g_cur4[NNODES*HD];
__device__ float g_tmp [NNODES*HD];
__device__ float g_kvt [32*16384];        // KV^T per (b,h): [e][d]
__device__ float g_pkv [NCH*32*16384];    // KV partials per chunk
__device__ float g_pv  [NCH*4096];        // vsum partials
__device__ float g_vsum[4096];
__device__ float g_ksp [NCH*4096];        // ksum partials
__device__ float g_ksum[4096];
__device__ float g_invden[NNODES*NH];
__device__ float g_dis [NNODES];
__device__ float g_w   [NEDGE];
__device__ int   g_cnt [NNODES];
__device__ int   g_rowptr[NNODES+1];
__device__ int   g_fill[NNODES];
__device__ int   g_bsum[NNODES/256];
__device__ int   g_col [NEDGE];
__device__ int   g_ekey[NEDGE];

// ----------------------------- TF32 helpers ----------------------------------
__device__ __forceinline__ uint32_t tf32r(float x) {
    uint32_t u;
    asm("cvt.rna.tf32.f32 %0, %1;" : "=r"(u) : "f"(x));
    return u;
}

#define MMA_TF32(cc, aa, b0v, b1v)                                              \
    asm volatile("mma.sync.aligned.m16n8k8.row.col.f32.tf32.tf32.f32 "          \
                 "{%0,%1,%2,%3}, {%4,%5,%6,%7}, {%8,%9}, {%0,%1,%2,%3};"        \
                 : "+f"((cc)[0]), "+f"((cc)[1]), "+f"((cc)[2]), "+f"((cc)[3])   \
                 : "r"((aa)[0]), "r"((aa)[1]), "r"((aa)[2]), "r"((aa)[3]),      \
                   "r"(b0v), "r"(b1v))

// MMA inner step over a staged 32-deep K slab (shared by all GEMM kernels).
#define GEMM_MMA_SLAB()                                                         \
    _Pragma("unroll")                                                           \
    for (int ks = 0; ks < 4; ks++) {                                            \
        int k0 = ks * 8;                                                        \
        uint32_t a[2][4];                                                       \
        _Pragma("unroll")                                                       \
        for (int mt = 0; mt < 2; mt++) {                                        \
            int m = mbase + mt * 16 + g;                                        \
            a[mt][0] = As[m    ][k0 + t];                                       \
            a[mt][1] = As[m + 8][k0 + t];                                       \
            a[mt][2] = As[m    ][k0 + t + 4];                                   \
            a[mt][3] = As[m + 8][k0 + t + 4];                                   \
        }                                                                       \
        _Pragma("unroll")                                                       \
        for (int nt = 0; nt < 8; nt++) {                                        \
            int n = nbase + nt * 8 + g;                                         \
            uint32_t b0 = Bs[n][k0 + t];                                        \
            uint32_t b1 = Bs[n][k0 + t + 4];                                    \
            MMA_TF32(c[0][nt], a[0], b0, b1);                                   \
            MMA_TF32(c[1][nt], a[1], b0, b1);                                   \
        }                                                                       \
    }

#define GEMM_MAINLOOP(Ab, lda, Bb, ldb, K)                                      \
    for (int kt = 0; kt < (K); kt += 32) {                                      \
        _Pragma("unroll")                                                       \
        for (int r = 0; r < 4; r++) {                                           \
            int idx = tid + r * 256;                                            \
            int row = idx >> 3;                                                 \
            int kq  = (idx & 7) << 2;                                           \
            float4 v = *(const float4*)&(Ab)[(long)(i0 + row) * (lda) + kt + kq]; \
            As[row][kq+0] = tf32r(v.x); As[row][kq+1] = tf32r(v.y);             \
            As[row][kq+2] = tf32r(v.z); As[row][kq+3] = tf32r(v.w);             \
            float4 w = *(const float4*)&(Bb)[(long)(j0 + row) * (ldb) + kt + kq]; \
            Bs[row][kq+0] = tf32r(w.x); Bs[row][kq+1] = tf32r(w.y);             \
            Bs[row][kq+2] = tf32r(w.z); Bs[row][kq+3] = tf32r(w.w);             \
        }                                                                       \
        __syncthreads();                                                        \
        GEMM_MMA_SLAB();                                                        \
        __syncthreads();                                                        \
    }

#define GEMM_PROLOGUE()                                                         \
    int tid = threadIdx.x;                                                      \
    int wid = tid >> 5, lane = tid & 31;                                        \
    int g = lane >> 2, t = lane & 3;                                            \
    int mbase = (wid & 3) * 32, nbase = (wid >> 2) * 64;                        \
    float c[2][8][4];                                                           \
    _Pragma("unroll")                                                           \
    for (int mt = 0; mt < 2; mt++)                                              \
        _Pragma("unroll")                                                       \
        for (int nt = 0; nt < 8; nt++)                                          \
            _Pragma("unroll")                                                   \
            for (int q = 0; q < 4; q++) c[mt][nt][q] = 0.f;

// ----------------------------- generic TC GEMM: C = scale*(A*B^T + bias) -----
__global__ void gemm_abT_tc(const float* __restrict__ A, int lda, long sOutA, long sInA,
                            const float* __restrict__ Bm, int ldb, long sOutB, long sInB,
                            const float* __restrict__ bias,
                            float* __restrict__ C, int ldc, long sOutC, long sInC,
                            int K, float scale)
{
    __shared__ uint32_t As[128][40];
    __shared__ uint32_t Bs[128][40];
    int z = blockIdx.z; int zb = z >> 2, zh = z & 3;
    const float* Ab = A  + zb*sOutA + zh*sInA;
    const float* Bb = Bm + zb*sOutB + zh*sInB;
    float*       Cb = C  + zb*sOutC + zh*sInC;
    int i0 = blockIdx.x * 128, j0 = blockIdx.y * 128;
    GEMM_PROLOGUE();
    GEMM_MAINLOOP(Ab, lda, Bb, ldb, K);
#pragma unroll
    for (int mt = 0; mt < 2; mt++) {
        int r0 = i0 + mbase + mt * 16 + g;
#pragma unroll
        for (int nt = 0; nt < 8; nt++) {
            int col = j0 + nbase + nt * 8 + 2 * t;
            float b0 = bias ? bias[col]     : 0.f;
            float b1 = bias ? bias[col + 1] : 0.f;
            float2 o;
            o.x = scale * (c[mt][nt][0] + b0);
            o.y = scale * (c[mt][nt][1] + b1);
            *(float2*)&Cb[(long)r0 * ldc + col] = o;
            o.x = scale * (c[mt][nt][2] + b0);
            o.y = scale * (c[mt][nt][3] + b1);
            *(float2*)&Cb[(long)(r0 + 8) * ldc + col] = o;
        }
    }
}

// ----------------------------- projection GEMM + register-space row norm -----
__global__ void gemm_abT_norm(const float* __restrict__ A,
                              const float* __restrict__ Wm,
                              const float* __restrict__ bias,
                              float* __restrict__ C)
{
    __shared__ uint32_t As[128][40];
    __shared__ uint32_t Bs[128][40];
    __shared__ float nrm[2][128];
    int i0 = blockIdx.x * 128, j0 = blockIdx.y * 128;
    GEMM_PROLOGUE();
    GEMM_MAINLOOP(A, DIM, Wm, DIM, DIM);

    int ng = wid >> 2;
    float ss[2][2] = {{0.f,0.f},{0.f,0.f}};
#pragma unroll
    for (int mt = 0; mt < 2; mt++)
#pragma unroll
        for (int nt = 0; nt < 8; nt++) {
            int col = j0 + nbase + nt * 8 + 2 * t;
            float b0 = bias[col], b1 = bias[col + 1];
            c[mt][nt][0] += b0; c[mt][nt][1] += b1;
            c[mt][nt][2] += b0; c[mt][nt][3] += b1;
            ss[mt][0] += c[mt][nt][0]*c[mt][nt][0] + c[mt][nt][1]*c[mt][nt][1];
            ss[mt][1] += c[mt][nt][2]*c[mt][nt][2] + c[mt][nt][3]*c[mt][nt][3];
        }
#pragma unroll
    for (int mt = 0; mt < 2; mt++)
#pragma unroll
        for (int hq = 0; hq < 2; hq++) {
            float v = ss[mt][hq];
            v += __shfl_xor_sync(0xffffffffu, v, 1);
            v += __shfl_xor_sync(0xffffffffu, v, 2);
            ss[mt][hq] = v;
        }
    if (t == 0) {
        nrm[ng][mbase + g]      = ss[0][0];
        nrm[ng][mbase + g + 8]  = ss[0][1];
        nrm[ng][mbase + 16 + g] = ss[1][0];
        nrm[ng][mbase + 24 + g] = ss[1][1];
    }
    __syncthreads();
    float rn[2][2];
    rn[0][0] = rsqrtf(nrm[0][mbase + g]      + nrm[1][mbase + g]);
    rn[0][1] = rsqrtf(nrm[0][mbase + g + 8]  + nrm[1][mbase + g + 8]);
    rn[1][0] = rsqrtf(nrm[0][mbase + 16 + g] + nrm[1][mbase + 16 + g]);
    rn[1][1] = rsqrtf(nrm[0][mbase + 24 + g] + nrm[1][mbase + 24 + g]);

#pragma unroll
    for (int mt = 0; mt < 2; mt++) {
        int r0 = i0 + mbase + mt * 16 + g;
#pragma unroll
        for (int nt = 0; nt < 8; nt++) {
            int col = j0 + nbase + nt * 8 + 2 * t;
            float2 o;
            o.x = c[mt][nt][0] * rn[mt][0];
            o.y = c[mt][nt][1] * rn[mt][0];
            *(float2*)&C[(long)r0 * HD + col] = o;
            o.x = c[mt][nt][2] * rn[mt][1];
            o.y = c[mt][nt][3] * rn[mt][1];
            *(float2*)&C[(long)(r0 + 8) * HD + col] = o;
        }
    }
}

// ----------------------------- output GEMM with on-the-fly acc sum -----------
// A = x_broadcast + c1 + c2 + c3 + c4 (left-to-right, bit-identical to the old
// incremental acc). out = scale*(A @ Wo^T + bias). grid (256,1,1), K = HD.
__global__ void gemm_out_sum(const float* __restrict__ x,
                             const float* __restrict__ c1, const float* __restrict__ c2,
                             const float* __restrict__ c3, const float* __restrict__ c4,
                             const float* __restrict__ Wm,
                             const float* __restrict__ bias,
                             float* __restrict__ C, float scale)
{
    __shared__ uint32_t As[128][40];
    __shared__ uint32_t Bs[128][40];
    int i0 = blockIdx.x * 128;
    GEMM_PROLOGUE();
    for (int kt = 0; kt < HD; kt += 32) {
#pragma unroll
        for (int r = 0; r < 4; r++) {
            int idx = tid + r * 256;
            int row = idx >> 3;
            int kq  = (idx & 7) << 2;
            int k   = kt + kq;
            long off = (long)(i0 + row) * HD + k;
            float4 vx = *(const float4*)&x[(long)(i0 + row) * DIM + (k & 127)];
            float4 v1 = *(const float4*)&c1[off];
            float4 v2 = *(const float4*)&c2[off];
            float4 v3 = *(const float4*)&c3[off];
            float4 v4 = *(const float4*)&c4[off];
            float4 s;
            s.x = (((vx.x + v1.x) + v2.x) + v3.x) + v4.x;
            s.y = (((vx.y + v1.y) + v2.y) + v3.y) + v4.y;
            s.z = (((vx.z + v1.z) + v2.z) + v3.z) + v4.z;
            s.w = (((vx.w + v1.w) + v2.w) + v3.w) + v4.w;
            As[row][kq+0] = tf32r(s.x); As[row][kq+1] = tf32r(s.y);
            As[row][kq+2] = tf32r(s.z); As[row][kq+3] = tf32r(s.w);
            float4 w = *(const float4*)&Wm[(long)row * HD + k];
            Bs[row][kq+0] = tf32r(w.x); Bs[row][kq+1] = tf32r(w.y);
            Bs[row][kq+2] = tf32r(w.z); Bs[row][kq+3] = tf32r(w.w);
        }
        __syncthreads();
        GEMM_MMA_SLAB();
        __syncthreads();
    }
#pragma unroll
    for (int mt = 0; mt < 2; mt++) {
        int r0 = i0 + mbase + mt * 16 + g;
#pragma unroll
        for (int nt = 0; nt < 8; nt++) {
            int col = nbase + nt * 8 + 2 * t;
            float b0 = bias[col], b1 = bias[col + 1];
            float2 o;
            o.x = scale * (c[mt][nt][0] + b0);
            o.y = scale * (c[mt][nt][1] + b1);
            *(float2*)&C[(long)r0 * DIM + col] = o;
            o.x = scale * (c[mt][nt][2] + b0);
            o.y = scale * (c[mt][nt][3] + b1);
            *(float2*)&C[(long)(r0 + 8) * DIM + col] = o;
        }
    }
}

// ----------------------------- ksum partials ---------------------------------
__global__ void ksum_partial_kernel()
{
    int chunk = blockIdx.x, bh = blockIdx.y;
    int b = bh >> 2, h = bh & 3, d = threadIdx.x;
    long base = ((long)b * NPG + chunk * CHN) * HD + h * DIM + d;
    float s = 0.f;
    for (int n = 0; n < CHN; n++) s += g_ks[base + (long)n * HD];
    g_ksp[(chunk * 32 + bh) * DIM + d] = s;
}

// deterministic fixed-order reduce of NCH chunk partials
__global__ void reduce_nch(const float* __restrict__ part, float* __restrict__ out, int n)
{
    int i = blockIdx.x * blockDim.x + threadIdx.x;
    if (i < n) {
        float s = 0.f;
#pragma unroll
        for (int c = 0; c < NCH; c++) s += part[(long)c * n + i];
        out[i] = s;
    }
}

// ----------------------------- inverse denominator (loop-invariant) ----------
__global__ void invden_kernel()
{
    int i = blockIdx.x;
    int h = threadIdx.x >> 5, l = threadIdx.x & 31;
    int b = i >> 12;  // /NPG
    float4 q = *(float4*)&g_qs[(long)i * HD + h * DIM + l * 4];
    float4 km = *(float4*)&g_ksum[(b * NH + h) * DIM + l * 4];
    float s = q.x*km.x + q.y*km.y + q.z*km.z + q.w*km.w;
#pragma unroll
    for (int o = 16; o; o >>= 1) s += __shfl_xor_sync(0xffffffffu, s, o);
    if (l == 0) g_invden[i * NH + h] = 1.f / (s + (float)NPG);
}

// ----------------------------- graph prep ------------------------------------
__global__ void count_kernel(const int* __restrict__ ei)
{
    int e = blockIdx.x * blockDim.x + threadIdx.x;
    if (e < NEDGE) atomicAdd(&g_cnt[ei[e]], 1);
}

__global__ void scan1_kernel()
{
    __shared__ int sh[256];
    int tid = threadIdx.x;
    int i = blockIdx.x * 256 + tid;
    int v = g_cnt[i];
    sh[tid] = v;
    __syncthreads();
    for (int o = 1; o < 256; o <<= 1) {
        int t = (tid >= o) ? sh[tid - o] : 0;
        __syncthreads();
        sh[tid] += t;
        __syncthreads();
    }
    g_rowptr[i] = sh[tid] - v;
    if (tid == 255) g_bsum[blockIdx.x] = sh[255];
}

__global__ void scan2_kernel()
{
    __shared__ int sh[128];
    int tid = threadIdx.x;
    int v = g_bsum[tid];
    sh[tid] = v;
    __syncthreads();
    for (int o = 1; o < 128; o <<= 1) {
        int t = (tid >= o) ? sh[tid - o] : 0;
        __syncthreads();
        sh[tid] += t;
        __syncthreads();
    }
    g_bsum[tid] = sh[tid] - v;
}

__global__ void scan3_kernel()
{
    int tid = threadIdx.x;
    int i = blockIdx.x * 256 + tid;
    g_rowptr[i] += g_bsum[blockIdx.x];
    int c = g_cnt[i];
    g_dis[i] = (c > 0) ? rsqrtf((float)c) : 0.f;
    if (i == 0) g_rowptr[NNODES] = NEDGE;
}

__global__ void scatter_kernel(const int* __restrict__ ei)
{
    int e = blockIdx.x * blockDim.x + threadIdx.x;
    if (e < NEDGE) {
        int r = ei[e], c = ei[NEDGE + e];
        int p = g_rowptr[r] + atomicAdd(&g_fill[r], 1);
        g_col[p] = c;
        g_ekey[p] = e;
    }
}

// canonicalize per-row edge order (determinism) + edge weights
__global__ void sortw_kernel()
{
    int i = blockIdx.x * blockDim.x + threadIdx.x;
    if (i >= NNODES) return;
    int s = g_rowptr[i], t = g_rowptr[i + 1];
    int n = t - s;
    float di = g_dis[i];
    if (n > 1 && n <= 64) {
        int kk[64], cc[64];
        for (int j = 0; j < n; j++) { kk[j] = g_ekey[s + j]; cc[j] = g_col[s + j]; }
        for (int a = 1; a < n; a++) {
            int kvv = kk[a], cv = cc[a], b = a - 1;
            while (b >= 0 && kk[b] > kvv) { kk[b+1] = kk[b]; cc[b+1] = cc[b]; b--; }
            kk[b+1] = kvv; cc[b+1] = cv;
        }
        for (int j = 0; j < n; j++) { g_col[s + j] = cc[j]; g_w[s + j] = di * g_dis[cc[j]]; }
    } else {
        for (int j = 0; j < n; j++) g_w[s + j] = di * g_dis[g_col[s + j]];
    }
}

// ----------------------------- init cur0 = broadcast(x) ----------------------
__global__ void init_kernel(const float* __restrict__ x)
{
    long gid = (long)blockIdx.x * blockDim.x + threadIdx.x;
    long f = gid * 4;
    int i = (int)(f >> 9);
    int d = (int)(f & 127);
    float4 v = *(const float4*)&x[(long)i * DIM + d];
    *(float4*)&g_cur0[f] = v;
}

// ----------------------------- per-iter: KV^T partials + vsum (tensor core) --
__global__ void kv_partial_tc(const float* __restrict__ cur)
{
    __shared__ uint32_t CU[32][136];   // [node][e]
    __shared__ uint32_t KS[32][136];   // [node][d]
    int chunk = blockIdx.x, bh = blockIdx.y;
    int b = bh >> 2, h = bh & 3;
    long nodeBase = (long)b * NPG + chunk * CHN;
    int tid = threadIdx.x;
    int wid = tid >> 5, lane = tid & 31;
    int g = lane >> 2, t = lane & 3;
    int mbase = (wid & 3) * 32, nbase = (wid >> 2) * 64;

    float c[2][8][4];
#pragma unroll
    for (int mt = 0; mt < 2; mt++)
#pragma unroll
        for (int nt = 0; nt < 8; nt++)
#pragma unroll
            for (int q = 0; q < 4; q++) c[mt][nt][q] = 0.f;
    float4 vs = make_float4(0.f, 0.f, 0.f, 0.f);

    for (int t0 = 0; t0 < CHN; t0 += 32) {
#pragma unroll
        for (int r = 0; r < 4; r++) {
            int idx = tid + r * 256;
            int nn = idx >> 5;
            int c4 = (idx & 31) * 4;
            long off = (nodeBase + t0 + nn) * HD + h * DIM + c4;
            float4 u  = *(const float4*)&cur[off];
            float4 k4 = *(const float4*)&g_ks[off];
            vs.x += u.x; vs.y += u.y; vs.z += u.z; vs.w += u.w;
            CU[nn][c4+0] = tf32r(u.x);  CU[nn][c4+1] = tf32r(u.y);
            CU[nn][c4+2] = tf32r(u.z);  CU[nn][c4+3] = tf32r(u.w);
            KS[nn][c4+0] = tf32r(k4.x); KS[nn][c4+1] = tf32r(k4.y);
            KS[nn][c4+2] = tf32r(k4.z); KS[nn][c4+3] = tf32r(k4.w);
        }
        __syncthreads();
#pragma unroll
        for (int ks = 0; ks < 4; ks++) {
            int k0 = ks * 8;
            uint32_t a[2][4];
#pragma unroll
            for (int mt = 0; mt < 2; mt++) {
                int m = mbase + mt * 16 + g;
                a[mt][0] = CU[k0 + t    ][m];
                a[mt][1] = CU[k0 + t    ][m + 8];
                a[mt][2] = CU[k0 + t + 4][m];
                a[mt][3] = CU[k0 + t + 4][m + 8];
            }
#pragma unroll
            for (int nt = 0; nt < 8; nt++) {
                int n = nbase + nt * 8 + g;
                uint32_t b0 = KS[k0 + t    ][n];
                uint32_t b1 = KS[k0 + t + 4][n];
                MMA_TF32(c[0][nt], a[0], b0, b1);
                MMA_TF32(c[1][nt], a[1], b0, b1);
            }
        }
        __syncthreads();
    }

    // vsum partial: fixed-order 8-way smem reduce
    {
        int cb = (tid & 31) * 4, rv = tid >> 5;
        CU[rv][cb+0] = __float_as_uint(vs.x);
        CU[rv][cb+1] = __float_as_uint(vs.y);
        CU[rv][cb+2] = __float_as_uint(vs.z);
        CU[rv][cb+3] = __float_as_uint(vs.w);
    }
    __syncthreads();
    if (tid < 128) {
        float s = 0.f;
#pragma unroll
        for (int j = 0; j < 8; j++) s += __uint_as_float(CU[j][tid]);
        g_pv[(chunk * 32 + bh) * 128 + tid] = s;
    }

    long base = ((long)chunk * 32 + bh) * 16384;
#pragma unroll
    for (int mt = 0; mt < 2; mt++) {
        int r0 = mbase + mt * 16 + g;
#pragma unroll
        for (int nt = 0; nt < 8; nt++) {
            int col = nbase + nt * 8 + 2 * t;
            float2 o;
            o.x = c[mt][nt][0]; o.y = c[mt][nt][1];
            *(float2*)&g_pkv[base + (long)r0 * 128 + col] = o;
            o.x = c[mt][nt][2]; o.y = c[mt][nt][3];
            *(float2*)&g_pkv[base + (long)(r0 + 8) * 128 + col] = o;
        }
    }
}

// ----------------------------- per-iter: GCN gather + attn combine -----------
__global__ void fuse_kernel(const float* __restrict__ cur, float* __restrict__ curn)
{
    int slot = threadIdx.x >> 6;       // 4 nodes per block
    int t = threadIdx.x & 63;          // 64 threads per node
    int i = blockIdx.x * 4 + slot;
    int b = i >> 12;
    int f0 = t * 4, f1 = t * 4 + 256;
    int s = g_rowptr[i], e = g_rowptr[i + 1];

    float4 gg0 = make_float4(0,0,0,0), gg1 = make_float4(0,0,0,0);
    for (int p = s; p < e; p++) {
        int c = g_col[p]; float w = g_w[p];
        const float* cr = cur + (long)c * HD;
        float4 a0 = *(const float4*)&cr[f0];
        float4 a1 = *(const float4*)&cr[f1];
        gg0.x += w * a0.x; gg0.y += w * a0.y; gg0.z += w * a0.z; gg0.w += w * a0.w;
        gg1.x += w * a1.x; gg1.y += w * a1.y; gg1.z += w * a1.z; gg1.w += w * a1.w;
    }
    int h0 = f0 >> 7, h1 = f1 >> 7;
    float id0 = g_invden[i * NH + h0];
    float id1 = g_invden[i * NH + h1];
    long ib = (long)i * HD;
    float4 t0 = *(const float4*)&g_tmp[ib + f0];
    float4 t1 = *(const float4*)&g_tmp[ib + f1];
    float4 v0 = *(const float4*)&g_vsum[(b * NH + h0) * DIM + (f0 & 127)];
    float4 v1 = *(const float4*)&g_vsum[(b * NH + h1) * DIM + (f1 & 127)];

    float4 r0, r1;
    r0.x = 0.5f*gg0.x + 0.5f*((t0.x + v0.x) * id0);
    r0.y = 0.5f*gg0.y + 0.5f*((t0.y + v0.y) * id0);
    r0.z = 0.5f*gg0.z + 0.5f*((t0.z + v0.z) * id0);
    r0.w = 0.5f*gg0.w + 0.5f*((t0.w + v0.w) * id0);
    r1.x = 0.5f*gg1.x + 0.5f*((t1.x + v1.x) * id1);
    r1.y = 0.5f*gg1.y + 0.5f*((t1.y + v1.y) * id1);
    r1.z = 0.5f*gg1.z + 0.5f*((t1.z + v1.z) * id1);
    r1.w = 0.5f*gg1.w + 0.5f*((t1.w + v1.w) * id1);

    *(float4*)&curn[ib + f0] = r0;
    *(float4*)&curn[ib + f1] = r1;
}

// ----------------------------- host orchestration ----------------------------
extern "C" void kernel_launch(void* const* d_in, const int* in_sizes, int n_in,
                              void* d_out, int out_size)
{
    const float* x    = (const float*)d_in[0];
    const float* Wq_w = (const float*)d_in[1];
    const float* Wq_b = (const float*)d_in[2];
    const float* Wk_w = (const float*)d_in[3];
    const float* Wk_b = (const float*)d_in[4];
    const float* Wo_w = (const float*)d_in[5];
    const float* Wo_b = (const float*)d_in[6];
    const int*   ei   = (const int*)  d_in[7];
    float* out = (float*)d_out;

    float *qs, *ks, *tmp, *kvt, *pkv, *pv, *vsum, *ksp, *ksum;
    float *curs[5];
    int *cnt, *fill;
    cudaGetSymbolAddress((void**)&qs,      g_qs);
    cudaGetSymbolAddress((void**)&ks,      g_ks);
    cudaGetSymbolAddress((void**)&curs[0], g_cur0);
    cudaGetSymbolAddress((void**)&curs[1], g_cur1);
    cudaGetSymbolAddress((void**)&curs[2], g_cur2);
    cudaGetSymbolAddress((void**)&curs[3], g_cur3);
    cudaGetSymbolAddress((void**)&curs[4], g_cur4);
    cudaGetSymbolAddress((void**)&tmp,     g_tmp);
    cudaGetSymbolAddress((void**)&kvt,     g_kvt);
    cudaGetSymbolAddress((void**)&pkv,     g_pkv);
    cudaGetSymbolAddress((void**)&pv,      g_pv);
    cudaGetSymbolAddress((void**)&vsum,    g_vsum);
    cudaGetSymbolAddress((void**)&ksp,     g_ksp);
    cudaGetSymbolAddress((void**)&ksum,    g_ksum);
    cudaGetSymbolAddress((void**)&cnt,     g_cnt);
    cudaGetSymbolAddress((void**)&fill,    g_fill);

    // Q/K projections fused with per-head row normalization (register-space)
    gemm_abT_norm<<<dim3(256,4,1),256>>>(x, Wq_w, Wq_b, qs);
    gemm_abT_norm<<<dim3(256,4,1),256>>>(x, Wk_w, Wk_b, ks);
    ksum_partial_kernel<<<dim3(NCH,32),128>>>();
    reduce_nch<<<16,256>>>(ksp, ksum, 4096);
    invden_kernel<<<NNODES,128>>>();

    // Graph prep: degrees, CSR, normalized weights (deterministic order)
    cudaMemsetAsync(cnt,  0, NNODES * sizeof(int));
    cudaMemsetAsync(fill, 0, NNODES * sizeof(int));
    count_kernel<<<NEDGE/256,256>>>(ei);
    scan1_kernel<<<NNODES/256,256>>>();
    scan2_kernel<<<1,128>>>();
    scan3_kernel<<<NNODES/256,256>>>();
    scatter_kernel<<<NEDGE/256,256>>>(ei);
    sortw_kernel<<<NNODES/128,128>>>();

    // cur0 = broadcast(x) over heads
    init_kernel<<<16384,256>>>(x);

    for (int it = 0; it < 4; it++) {
        kv_partial_tc<<<dim3(NCH,32),256>>>(curs[it]);
        reduce_nch<<<2048,256>>>(pkv, kvt, 32*16384);
        reduce_nch<<<16,256>>>(pv, vsum, 4096);
        // tmp[n, h*128+e] = qs[n, h*128+:] @ KV  (batched over 32 (b,h))
        gemm_abT_tc<<<dim3(32,1,32),256>>>(qs, HD, (long)NPG*HD, DIM,
                                           kvt, DIM, 4L*16384, 16384,
                                           nullptr,
                                           tmp, HD, (long)NPG*HD, DIM,
                                           DIM, 1.f);
        fuse_kernel<<<NNODES/4,256>>>(curs[it], curs[it+1]);
    }

    // out = ((x_bcast + c1 + c2 + c3 + c4) @ Wo^T + Wo_b) / H
    gemm_out_sum<<<dim3(256,1,1),256>>>(x, curs[1], curs[2], curs[3], curs[4],
                                        Wo_w, Wo_b, out, 0.25f);
    (void)in_sizes; (void)n_in; (void)out_size;
}

// round 13
// speedup vs baseline: 1.4375x; 1.0846x over previous
#include <cuda_runtime.h>
#include <cstdint>

// Problem constants (fixed by setup_inputs)
#define NNODES 32768
#define DIM    128
#define NH     4
#define HD     512      // NH*DIM
#define NEDGE  262144
#define NGRAPH 8
#define NPG    4096
#define NCH    8        // chunks per (b,h) for KV partials
#define CHN    512      // nodes per chunk (NPG/NCH)

// ----------------------------- scratch (static device globals) ---------------
__device__ float g_qs  [NNODES*HD];
__device__ float g_ks  [NNODES*HD];
__device__ float g_cur1[NNODES*HD];     // cur_t, t=1..4 (t=0 is x broadcast)
__device__ float g_cur2[NNODES*HD];
__device__ float g_cur3[NNODES*HD];
__device__ float g_cur4[NNODES*HD];
__device__ float g_tmp [NNODES*HD];
__device__ float g_kvt [32*16384];        // KV^T per (b,h): [e][d]
__device__ float g_pkv [NCH*32*16384];    // KV partials per chunk
__device__ float g_pv  [NCH*4096];        // vsum partials
__device__ float g_vsum[4096];
__device__ float g_ksp [NCH*4096];        // ksum partials
__device__ float g_ksum[4096];
__device__ float g_invden[NNODES*NH];
__device__ float g_dis [NNODES];
__device__ float g_w   [NEDGE];
__device__ int   g_ctr [32];              // arrival counters (self-resetting)
__device__ int   g_cnt [NNODES];
__device__ int   g_rowptr[NNODES+1];
__device__ int   g_fill[NNODES];
__device__ int   g_bsum[NNODES/256];
__device__ int   g_col [NEDGE];
__device__ int   g_ekey[NEDGE];

// ----------------------------- TF32 helpers ----------------------------------
__device__ __forceinline__ uint32_t tf32r(float x) {
    uint32_t u;
    asm("cvt.rna.tf32.f32 %0, %1;" : "=r"(u) : "f"(x));
    return u;
}

#define MMA_TF32(cc, aa, b0v, b1v)                                              \
    asm volatile("mma.sync.aligned.m16n8k8.row.col.f32.tf32.tf32.f32 "          \
                 "{%0,%1,%2,%3}, {%4,%5,%6,%7}, {%8,%9}, {%0,%1,%2,%3};"        \
                 : "+f"((cc)[0]), "+f"((cc)[1]), "+f"((cc)[2]), "+f"((cc)[3])   \
                 : "r"((aa)[0]), "r"((aa)[1]), "r"((aa)[2]), "r"((aa)[3]),      \
                   "r"(b0v), "r"(b1v))

// MMA inner step over a staged 32-deep K slab (shared by all GEMM kernels).
#define GEMM_MMA_SLAB()                                                         \
    _Pragma("unroll")                                                           \
    for (int ks = 0; ks < 4; ks++) {                                            \
        int k0 = ks * 8;                                                        \
        uint32_t a[2][4];                                                       \
        _Pragma("unroll")                                                       \
        for (int mt = 0; mt < 2; mt++) {                                        \
            int m = mbase + mt * 16 + g;                                        \
            a[mt][0] = As[m    ][k0 + t];                                       \
            a[mt][1] = As[m + 8][k0 + t];                                       \
            a[mt][2] = As[m    ][k0 + t + 4];                                   \
            a[mt][3] = As[m + 8][k0 + t + 4];                                   \
        }                                                                       \
        _Pragma("unroll")                                                       \
        for (int nt = 0; nt < 8; nt++) {                                        \
            int n = nbase + nt * 8 + g;                                         \
            uint32_t b0 = Bs[n][k0 + t];                                        \
            uint32_t b1 = Bs[n][k0 + t + 4];                                    \
            MMA_TF32(c[0][nt], a[0], b0, b1);                                   \
            MMA_TF32(c[1][nt], a[1], b0, b1);                                   \
        }                                                                       \
    }

#define GEMM_MAINLOOP(Ab, lda, Bb, ldb, K)                                      \
    for (int kt = 0; kt < (K); kt += 32) {                                      \
        _Pragma("unroll")                                                       \
        for (int r = 0; r < 4; r++) {                                           \
            int idx = tid + r * 256;                                            \
            int row = idx >> 3;                                                 \
            int kq  = (idx & 7) << 2;                                           \
            float4 v = *(const float4*)&(Ab)[(long)(i0 + row) * (lda) + kt + kq]; \
            As[row][kq+0] = tf32r(v.x); As[row][kq+1] = tf32r(v.y);             \
            As[row][kq+2] = tf32r(v.z); As[row][kq+3] = tf32r(v.w);             \
            float4 w = *(const float4*)&(Bb)[(long)(j0 + row) * (ldb) + kt + kq]; \
            Bs[row][kq+0] = tf32r(w.x); Bs[row][kq+1] = tf32r(w.y);             \
            Bs[row][kq+2] = tf32r(w.z); Bs[row][kq+3] = tf32r(w.w);             \
        }                                                                       \
        __syncthreads();                                                        \
        GEMM_MMA_SLAB();                                                        \
        __syncthreads();                                                        \
    }

#define GEMM_PROLOGUE()                                                         \
    int tid = threadIdx.x;                                                      \
    int wid = tid >> 5, lane = tid & 31;                                        \
    int g = lane >> 2, t = lane & 3;                                            \
    int mbase = (wid & 3) * 32, nbase = (wid >> 2) * 64;                        \
    float c[2][8][4];                                                           \
    _Pragma("unroll")                                                           \
    for (int mt = 0; mt < 2; mt++)                                              \
        _Pragma("unroll")                                                       \
        for (int nt = 0; nt < 8; nt++)                                          \
            _Pragma("unroll")                                                   \
            for (int q = 0; q < 4; q++) c[mt][nt][q] = 0.f;

// ----------------------------- generic TC GEMM: C = scale*(A*B^T + bias) -----
__global__ void gemm_abT_tc(const float* __restrict__ A, int lda, long sOutA, long sInA,
                            const float* __restrict__ Bm, int ldb, long sOutB, long sInB,
                            const float* __restrict__ bias,
                            float* __restrict__ C, int ldc, long sOutC, long sInC,
                            int K, float scale)
{
    __shared__ uint32_t As[128][40];
    __shared__ uint32_t Bs[128][40];
    int z = blockIdx.z; int zb = z >> 2, zh = z & 3;
    const float* Ab = A  + zb*sOutA + zh*sInA;
    const float* Bb = Bm + zb*sOutB + zh*sInB;
    float*       Cb = C  + zb*sOutC + zh*sInC;
    int i0 = blockIdx.x * 128, j0 = blockIdx.y * 128;
    GEMM_PROLOGUE();
    GEMM_MAINLOOP(Ab, lda, Bb, ldb, K);
#pragma unroll
    for (int mt = 0; mt < 2; mt++) {
        int r0 = i0 + mbase + mt * 16 + g;
#pragma unroll
        for (int nt = 0; nt < 8; nt++) {
            int col = j0 + nbase + nt * 8 + 2 * t;
            float b0 = bias ? bias[col]     : 0.f;
            float b1 = bias ? bias[col + 1] : 0.f;
            float2 o;
            o.x = scale * (c[mt][nt][0] + b0);
            o.y = scale * (c[mt][nt][1] + b1);
            *(float2*)&Cb[(long)r0 * ldc + col] = o;
            o.x = scale * (c[mt][nt][2] + b0);
            o.y = scale * (c[mt][nt][3] + b1);
            *(float2*)&Cb[(long)(r0 + 8) * ldc + col] = o;
        }
    }
}

// ----------------------------- projection GEMM + row norm (+ optional invden)
// C = normalize_rows(A*W^T + bias) per head. grid (256, NH); blockIdx.y = head.
// If ksum != nullptr, also writes g_invden[row*NH+h] = 1/(q_hat . ksum + NPG).
__global__ void gemm_abT_norm(const float* __restrict__ A,
                              const float* __restrict__ Wm,
                              const float* __restrict__ bias,
                              float* __restrict__ C,
                              const float* __restrict__ ksum)
{
    __shared__ uint32_t As[128][40];
    __shared__ uint32_t Bs[128][40];
    __shared__ float nrm[2][128];
    __shared__ float nd [2][128];
    int i0 = blockIdx.x * 128, j0 = blockIdx.y * 128;
    GEMM_PROLOGUE();
    GEMM_MAINLOOP(A, DIM, Wm, DIM, DIM);

    int ng = wid >> 2;
    float ss[2][2] = {{0.f,0.f},{0.f,0.f}};
#pragma unroll
    for (int mt = 0; mt < 2; mt++)
#pragma unroll
        for (int nt = 0; nt < 8; nt++) {
            int col = j0 + nbase + nt * 8 + 2 * t;
            float b0 = bias[col], b1 = bias[col + 1];
            c[mt][nt][0] += b0; c[mt][nt][1] += b1;
            c[mt][nt][2] += b0; c[mt][nt][3] += b1;
            ss[mt][0] += c[mt][nt][0]*c[mt][nt][0] + c[mt][nt][1]*c[mt][nt][1];
            ss[mt][1] += c[mt][nt][2]*c[mt][nt][2] + c[mt][nt][3]*c[mt][nt][3];
        }
#pragma unroll
    for (int mt = 0; mt < 2; mt++)
#pragma unroll
        for (int hq = 0; hq < 2; hq++) {
            float v = ss[mt][hq];
            v += __shfl_xor_sync(0xffffffffu, v, 1);
            v += __shfl_xor_sync(0xffffffffu, v, 2);
            ss[mt][hq] = v;
        }
    if (t == 0) {
        nrm[ng][mbase + g]      = ss[0][0];
        nrm[ng][mbase + g + 8]  = ss[0][1];
        nrm[ng][mbase + 16 + g] = ss[1][0];
        nrm[ng][mbase + 24 + g] = ss[1][1];
    }
    __syncthreads();
    float rn[2][2];
    rn[0][0] = rsqrtf(nrm[0][mbase + g]      + nrm[1][mbase + g]);
    rn[0][1] = rsqrtf(nrm[0][mbase + g + 8]  + nrm[1][mbase + g + 8]);
    rn[1][0] = rsqrtf(nrm[0][mbase + 16 + g] + nrm[1][mbase + 16 + g]);
    rn[1][1] = rsqrtf(nrm[0][mbase + 24 + g] + nrm[1][mbase + 24 + g]);

    int b = i0 >> 12;
    const float* km = ksum ? (ksum + (b * NH + blockIdx.y) * DIM) : nullptr;
    float dd[2][2] = {{0.f,0.f},{0.f,0.f}};
#pragma unroll
    for (int mt = 0; mt < 2; mt++) {
        int r0 = i0 + mbase + mt * 16 + g;
#pragma unroll
        for (int nt = 0; nt < 8; nt++) {
            int colh = nbase + nt * 8 + 2 * t;
            int col = j0 + colh;
            float2 o;
            o.x = c[mt][nt][0] * rn[mt][0];
            o.y = c[mt][nt][1] * rn[mt][0];
            *(float2*)&C[(long)r0 * HD + col] = o;
            float2 p;
            p.x = c[mt][nt][2] * rn[mt][1];
            p.y = c[mt][nt][3] * rn[mt][1];
            *(float2*)&C[(long)(r0 + 8) * HD + col] = p;
            if (km) {
                float k0 = km[colh], k1 = km[colh + 1];
                dd[mt][0] += o.x * k0 + o.y * k1;
                dd[mt][1] += p.x * k0 + p.y * k1;
            }
        }
    }
    if (km) {
#pragma unroll
        for (int mt = 0; mt < 2; mt++)
#pragma unroll
            for (int hq = 0; hq < 2; hq++) {
                float v = dd[mt][hq];
                v += __shfl_xor_sync(0xffffffffu, v, 1);
                v += __shfl_xor_sync(0xffffffffu, v, 2);
                dd[mt][hq] = v;
            }
        if (t == 0) {
            nd[ng][mbase + g]      = dd[0][0];
            nd[ng][mbase + g + 8]  = dd[0][1];
            nd[ng][mbase + 16 + g] = dd[1][0];
            nd[ng][mbase + 24 + g] = dd[1][1];
        }
        __syncthreads();
        if (ng == 0 && t == 0) {
            int rows[4] = {mbase + g, mbase + g + 8, mbase + 16 + g, mbase + 24 + g};
#pragma unroll
            for (int q = 0; q < 4; q++) {
                float dot = nd[0][rows[q]] + nd[1][rows[q]];
                g_invden[(i0 + rows[q]) * NH + blockIdx.y] = 1.f / (dot + (float)NPG);
            }
        }
    }
}

// ----------------------------- output GEMM with on-the-fly acc sum -----------
__global__ void gemm_out_sum(const float* __restrict__ x,
                             const float* __restrict__ c1, const float* __restrict__ c2,
                             const float* __restrict__ c3, const float* __restrict__ c4,
                             const float* __restrict__ Wm,
                             const float* __restrict__ bias,
                             float* __restrict__ C, float scale)
{
    __shared__ uint32_t As[128][40];
    __shared__ uint32_t Bs[128][40];
    int i0 = blockIdx.x * 128;
    GEMM_PROLOGUE();
    for (int kt = 0; kt < HD; kt += 32) {
#pragma unroll
        for (int r = 0; r < 4; r++) {
            int idx = tid + r * 256;
            int row = idx >> 3;
            int kq  = (idx & 7) << 2;
            int k   = kt + kq;
            long off = (long)(i0 + row) * HD + k;
            float4 vx = *(const float4*)&x[(long)(i0 + row) * DIM + (k & 127)];
            float4 v1 = *(const float4*)&c1[off];
            float4 v2 = *(const float4*)&c2[off];
            float4 v3 = *(const float4*)&c3[off];
            float4 v4 = *(const float4*)&c4[off];
            float4 s;
            s.x = (((vx.x + v1.x) + v2.x) + v3.x) + v4.x;
            s.y = (((vx.y + v1.y) + v2.y) + v3.y) + v4.y;
            s.z = (((vx.z + v1.z) + v2.z) + v3.z) + v4.z;
            s.w = (((vx.w + v1.w) + v2.w) + v3.w) + v4.w;
            As[row][kq+0] = tf32r(s.x); As[row][kq+1] = tf32r(s.y);
            As[row][kq+2] = tf32r(s.z); As[row][kq+3] = tf32r(s.w);
            float4 w = *(const float4*)&Wm[(long)row * HD + k];
            Bs[row][kq+0] = tf32r(w.x); Bs[row][kq+1] = tf32r(w.y);
            Bs[row][kq+2] = tf32r(w.z); Bs[row][kq+3] = tf32r(w.w);
        }
        __syncthreads();
        GEMM_MMA_SLAB();
        __syncthreads();
    }
#pragma unroll
    for (int mt = 0; mt < 2; mt++) {
        int r0 = i0 + mbase + mt * 16 + g;
#pragma unroll
        for (int nt = 0; nt < 8; nt++) {
            int col = nbase + nt * 8 + 2 * t;
            float b0 = bias[col], b1 = bias[col + 1];
            float2 o;
            o.x = scale * (c[mt][nt][0] + b0);
            o.y = scale * (c[mt][nt][1] + b1);
            *(float2*)&C[(long)r0 * DIM + col] = o;
            o.x = scale * (c[mt][nt][2] + b0);
            o.y = scale * (c[mt][nt][3] + b1);
            *(float2*)&C[(long)(r0 + 8) * DIM + col] = o;
        }
    }
}

// ----------------------------- ksum partials + fixed-order reduce ------------
__global__ void ksum_partial_kernel()
{
    int chunk = blockIdx.x, bh = blockIdx.y;
    int b = bh >> 2, h = bh & 3, d = threadIdx.x;
    long base = ((long)b * NPG + chunk * CHN) * HD + h * DIM + d;
    float s = 0.f;
    for (int n = 0; n < CHN; n++) s += g_ks[base + (long)n * HD];
    g_ksp[(chunk * 32 + bh) * DIM + d] = s;
}

__global__ void reduce_ksum()
{
    int i = blockIdx.x * blockDim.x + threadIdx.x;
    float s = 0.f;
#pragma unroll
    for (int c = 0; c < NCH; c++) s += g_ksp[(long)c * 4096 + i];
    g_ksum[i] = s;
}

// ----------------------------- graph prep ------------------------------------
__global__ void count_kernel(const int* __restrict__ ei)
{
    int e = blockIdx.x * blockDim.x + threadIdx.x;
    if (e < NEDGE) atomicAdd(&g_cnt[ei[e]], 1);
}

__global__ void scan1_kernel()
{
    __shared__ int sh[256];
    int tid = threadIdx.x;
    int i = blockIdx.x * 256 + tid;
    int v = g_cnt[i];
    sh[tid] = v;
    __syncthreads();
    for (int o = 1; o < 256; o <<= 1) {
        int t = (tid >= o) ? sh[tid - o] : 0;
        __syncthreads();
        sh[tid] += t;
        __syncthreads();
    }
    g_rowptr[i] = sh[tid] - v;
    if (tid == 255) g_bsum[blockIdx.x] = sh[255];
}

__global__ void scan2_kernel()
{
    __shared__ int sh[128];
    int tid = threadIdx.x;
    int v = g_bsum[tid];
    sh[tid] = v;
    __syncthreads();
    for (int o = 1; o < 128; o <<= 1) {
        int t = (tid >= o) ? sh[tid - o] : 0;
        __syncthreads();
        sh[tid] += t;
        __syncthreads();
    }
    g_bsum[tid] = sh[tid] - v;
}

__global__ void scan3_kernel()
{
    int tid = threadIdx.x;
    int i = blockIdx.x * 256 + tid;
    g_rowptr[i] += g_bsum[blockIdx.x];
    int c = g_cnt[i];
    g_dis[i] = (c > 0) ? rsqrtf((float)c) : 0.f;
    if (i == 0) g_rowptr[NNODES] = NEDGE;
}

__global__ void scatter_kernel(const int* __restrict__ ei)
{
    int e = blockIdx.x * blockDim.x + threadIdx.x;
    if (e < NEDGE) {
        int r = ei[e], c = ei[NEDGE + e];
        int p = g_rowptr[r] + atomicAdd(&g_fill[r], 1);
        g_col[p] = c;
        g_ekey[p] = e;
    }
}

// canonicalize per-row edge order (determinism) + edge weights
__global__ void sortw_kernel()
{
    int i = blockIdx.x * blockDim.x + threadIdx.x;
    if (i >= NNODES) return;
    int s = g_rowptr[i], t = g_rowptr[i + 1];
    int n = t - s;
    float di = g_dis[i];
    if (n > 1 && n <= 64) {
        int kk[64], cc[64];
        for (int j = 0; j < n; j++) { kk[j] = g_ekey[s + j]; cc[j] = g_col[s + j]; }
        for (int a = 1; a < n; a++) {
            int kvv = kk[a], cv = cc[a], b = a - 1;
            while (b >= 0 && kk[b] > kvv) { kk[b+1] = kk[b]; cc[b+1] = cc[b]; b--; }
            kk[b+1] = kvv; cc[b+1] = cv;
        }
        for (int j = 0; j < n; j++) { g_col[s + j] = cc[j]; g_w[s + j] = di * g_dis[cc[j]]; }
    } else {
        for (int j = 0; j < n; j++) g_w[s + j] = di * g_dis[g_col[s + j]];
    }
}

// ----------------------------- per-iter: KV^T partials + fused reduction -----
// cur addressing: node*cs + hsel + c4 (bcast: cs=DIM, hsel=0 reads x directly).
// Last-arriving block per bh reduces pkv->kvt and pv->vsum in fixed chunk
// order (deterministic), then resets its counter (zero-invariant per replay).
__global__ void kv_partial_tc(const float* __restrict__ cur, int bcast)
{
    __shared__ uint32_t CU[32][136];   // [node][e]
    __shared__ uint32_t KS[32][136];   // [node][d]
    __shared__ int sh_last;
    int chunk = blockIdx.x, bh = blockIdx.y;
    int b = bh >> 2, h = bh & 3;
    long nodeBase = (long)b * NPG + chunk * CHN;
    int cs   = bcast ? DIM : HD;
    int hsel = bcast ? 0   : h * DIM;
    int tid = threadIdx.x;
    int wid = tid >> 5, lane = tid & 31;
    int g = lane >> 2, t = lane & 3;
    int mbase = (wid & 3) * 32, nbase = (wid >> 2) * 64;

    float c[2][8][4];
#pragma unroll
    for (int mt = 0; mt < 2; mt++)
#pragma unroll
        for (int nt = 0; nt < 8; nt++)
#pragma unroll
            for (int q = 0; q < 4; q++) c[mt][nt][q] = 0.f;
    float4 vs = make_float4(0.f, 0.f, 0.f, 0.f);

    for (int t0 = 0; t0 < CHN; t0 += 32) {
#pragma unroll
        for (int r = 0; r < 4; r++) {
            int idx = tid + r * 256;
            int nn = idx >> 5;
            int c4 = (idx & 31) * 4;
            long node = nodeBase + t0 + nn;
            float4 u  = *(const float4*)&cur[node * cs + hsel + c4];
            float4 k4 = *(const float4*)&g_ks[node * HD + h * DIM + c4];
            vs.x += u.x; vs.y += u.y; vs.z += u.z; vs.w += u.w;
            CU[nn][c4+0] = tf32r(u.x);  CU[nn][c4+1] = tf32r(u.y);
            CU[nn][c4+2] = tf32r(u.z);  CU[nn][c4+3] = tf32r(u.w);
            KS[nn][c4+0] = tf32r(k4.x); KS[nn][c4+1] = tf32r(k4.y);
            KS[nn][c4+2] = tf32r(k4.z); KS[nn][c4+3] = tf32r(k4.w);
        }
        __syncthreads();
#pragma unroll
        for (int ks = 0; ks < 4; ks++) {
            int k0 = ks * 8;
            uint32_t a[2][4];
#pragma unroll
            for (int mt = 0; mt < 2; mt++) {
                int m = mbase + mt * 16 + g;
                a[mt][0] = CU[k0 + t    ][m];
                a[mt][1] = CU[k0 + t    ][m + 8];
                a[mt][2] = CU[k0 + t + 4][m];
                a[mt][3] = CU[k0 + t + 4][m + 8];
            }
#pragma unroll
            for (int nt = 0; nt < 8; nt++) {
                int n = nbase + nt * 8 + g;
                uint32_t b0 = KS[k0 + t    ][n];
                uint32_t b1 = KS[k0 + t + 4][n];
                MMA_TF32(c[0][nt], a[0], b0, b1);
                MMA_TF32(c[1][nt], a[1], b0, b1);
            }
        }
        __syncthreads();
    }

    // vsum partial: fixed-order 8-way smem reduce
    {
        int cb = (tid & 31) * 4, rv = tid >> 5;
        CU[rv][cb+0] = __float_as_uint(vs.x);
        CU[rv][cb+1] = __float_as_uint(vs.y);
        CU[rv][cb+2] = __float_as_uint(vs.z);
        CU[rv][cb+3] = __float_as_uint(vs.w);
    }
    __syncthreads();
    if (tid < 128) {
        float s = 0.f;
#pragma unroll
        for (int j = 0; j < 8; j++) s += __uint_as_float(CU[j][tid]);
        g_pv[(chunk * 32 + bh) * 128 + tid] = s;
    }

    long base = ((long)chunk * 32 + bh) * 16384;
#pragma unroll
    for (int mt = 0; mt < 2; mt++) {
        int r0 = mbase + mt * 16 + g;
#pragma unroll
        for (int nt = 0; nt < 8; nt++) {
            int col = nbase + nt * 8 + 2 * t;
            float2 o;
            o.x = c[mt][nt][0]; o.y = c[mt][nt][1];
            *(float2*)&g_pkv[base + (long)r0 * 128 + col] = o;
            o.x = c[mt][nt][2]; o.y = c[mt][nt][3];
            *(float2*)&g_pkv[base + (long)(r0 + 8) * 128 + col] = o;
        }
    }

    // fused deterministic reduction by the last-arriving block for this bh
    __threadfence();
    __syncthreads();
    if (tid == 0)
        sh_last = (atomicAdd(&g_ctr[bh], 1) == NCH - 1);
    __syncthreads();
    if (sh_last) {
        for (int i = tid; i < 16384; i += 256) {
            float s = 0.f;
#pragma unroll
            for (int cc = 0; cc < NCH; cc++)
                s += g_pkv[((long)cc * 32 + bh) * 16384 + i];
            g_kvt[(long)bh * 16384 + i] = s;
        }
        if (tid < 128) {
            float s = 0.f;
#pragma unroll
            for (int cc = 0; cc < NCH; cc++)
                s += g_pv[(cc * 32 + bh) * 128 + tid];
            g_vsum[bh * 128 + tid] = s;
        }
        __syncthreads();
        if (tid == 0) g_ctr[bh] = 0;   // restore invariant for next replay/iter
    }
}

// ----------------------------- per-iter: GCN gather + attn combine -----------
__global__ void fuse_kernel(const float* __restrict__ cur, int cs, int cmask,
                            float* __restrict__ curn)
{
    int slot = threadIdx.x >> 6;       // 4 nodes per block
    int t = threadIdx.x & 63;          // 64 threads per node
    int i = blockIdx.x * 4 + slot;
    int b = i >> 12;
    int f0 = t * 4, f1 = t * 4 + 256;
    int s = g_rowptr[i], e = g_rowptr[i + 1];

    float4 gg0 = make_float4(0,0,0,0), gg1 = make_float4(0,0,0,0);
    for (int p = s; p < e; p++) {
        int c = g_col[p]; float w = g_w[p];
        const float* cr = cur + (long)c * cs;
        float4 a0 = *(const float4*)&cr[f0 & cmask];
        float4 a1 = *(const float4*)&cr[f1 & cmask];
        gg0.x += w * a0.x; gg0.y += w * a0.y; gg0.z += w * a0.z; gg0.w += w * a0.w;
        gg1.x += w * a1.x; gg1.y += w * a1.y; gg1.z += w * a1.z; gg1.w += w * a1.w;
    }
    int h0 = f0 >> 7, h1 = f1 >> 7;
    float id0 = g_invden[i * NH + h0];
    float id1 = g_invden[i * NH + h1];
    long ib = (long)i * HD;
    float4 t0 = *(const float4*)&g_tmp[ib + f0];
    float4 t1 = *(const float4*)&g_tmp[ib + f1];
    float4 v0 = *(const float4*)&g_vsum[(b * NH + h0) * DIM + (f0 & 127)];
    float4 v1 = *(const float4*)&g_vsum[(b * NH + h1) * DIM + (f1 & 127)];

    float4 r0, r1;
    r0.x = 0.5f*gg0.x + 0.5f*((t0.x + v0.x) * id0);
    r0.y = 0.5f*gg0.y + 0.5f*((t0.y + v0.y) * id0);
    r0.z = 0.5f*gg0.z + 0.5f*((t0.z + v0.z) * id0);
    r0.w = 0.5f*gg0.w + 0.5f*((t0.w + v0.w) * id0);
    r1.x = 0.5f*gg1.x + 0.5f*((t1.x + v1.x) * id1);
    r1.y = 0.5f*gg1.y + 0.5f*((t1.y + v1.y) * id1);
    r1.z = 0.5f*gg1.z + 0.5f*((t1.z + v1.z) * id1);
    r1.w = 0.5f*gg1.w + 0.5f*((t1.w + v1.w) * id1);

    *(float4*)&curn[ib + f0] = r0;
    *(float4*)&curn[ib + f1] = r1;
}

// ----------------------------- host orchestration ----------------------------
extern "C" void kernel_launch(void* const* d_in, const int* in_sizes, int n_in,
                              void* d_out, int out_size)
{
    const float* x    = (const float*)d_in[0];
    const float* Wq_w = (const float*)d_in[1];
    const float* Wq_b = (const float*)d_in[2];
    const float* Wk_w = (const float*)d_in[3];
    const float* Wk_b = (const float*)d_in[4];
    const float* Wo_w = (const float*)d_in[5];
    const float* Wo_b = (const float*)d_in[6];
    const int*   ei   = (const int*)  d_in[7];
    float* out = (float*)d_out;

    float *qs, *ks, *tmp, *kvt, *ksum;
    float *curs[5];
    int *cnt, *fill;
    cudaGetSymbolAddress((void**)&qs,      g_qs);
    cudaGetSymbolAddress((void**)&ks,      g_ks);
    cudaGetSymbolAddress((void**)&curs[1], g_cur1);
    cudaGetSymbolAddress((void**)&curs[2], g_cur2);
    cudaGetSymbolAddress((void**)&curs[3], g_cur3);
    cudaGetSymbolAddress((void**)&curs[4], g_cur4);
    cudaGetSymbolAddress((void**)&tmp,     g_tmp);
    cudaGetSymbolAddress((void**)&kvt,     g_kvt);
    cudaGetSymbolAddress((void**)&ksum,    g_ksum);
    cudaGetSymbolAddress((void**)&cnt,     g_cnt);
    cudaGetSymbolAddress((void**)&fill,    g_fill);
    curs[0] = const_cast<float*>(x);   // iteration 0 reads x broadcast

    // K projection -> ksum -> Q projection (with fused invden)
    gemm_abT_norm<<<dim3(256,4,1),256>>>(x, Wk_w, Wk_b, ks, nullptr);
    ksum_partial_kernel<<<dim3(NCH,32),128>>>();
    reduce_ksum<<<16,256>>>();
    gemm_abT_norm<<<dim3(256,4,1),256>>>(x, Wq_w, Wq_b, qs, ksum);

    // Graph prep: degrees, CSR, normalized weights (deterministic order)
    cudaMemsetAsync(cnt,  0, NNODES * sizeof(int));
    cudaMemsetAsync(fill, 0, NNODES * sizeof(int));
    count_kernel<<<NEDGE/256,256>>>(ei);
    scan1_kernel<<<NNODES/256,256>>>();
    scan2_kernel<<<1,128>>>();
    scan3_kernel<<<NNODES/256,256>>>();
    scatter_kernel<<<NEDGE/256,256>>>(ei);
    sortw_kernel<<<NNODES/128,128>>>();

    for (int it = 0; it < 4; it++) {
        int bcast = (it == 0);
        kv_partial_tc<<<dim3(NCH,32),256>>>(curs[it], bcast);
        // tmp[n, h*128+e] = qs[n, h*128+:] @ KV  (batched over 32 (b,h))
        gemm_abT_tc<<<dim3(32,1,32),256>>>(qs, HD, (long)NPG*HD, DIM,
                                           kvt, DIM, 4L*16384, 16384,
                                           nullptr,
                                           tmp, HD, (long)NPG*HD, DIM,
                                           DIM, 1.f);
        fuse_kernel<<<NNODES/4,256>>>(curs[it], bcast ? DIM : HD,
                                      bcast ? 127 : 511, curs[it+1]);
    }

    // out = ((x_bcast + c1 + c2 + c3 + c4) @ Wo^T + Wo_b) / H
    gemm_out_sum<<<dim3(256,1,1),256>>>(x, curs[1], curs[2], curs[3], curs[4],
                                        Wo_w, Wo_b, out, 0.25f);
    (void)in_sizes; (void)n_in; (void)out_size;
}